// round 4
// baseline (speedup 1.0000x reference)
#include <cuda_runtime.h>
#include <math.h>
#include <stdint.h>

#define BATCH   8
#define SEQLEN  1024
#define NTOK    (BATCH*SEQLEN)     // 8192
#define DMODEL  512
#define DSTATE  64
#define DINNER  1024
#define NHEADS  16
#define HEADDIM 64
#define DINPROJ 2192               // 2*DINNER + CONVDIM + NHEADS
#define CONVDIM 1152               // DINNER + 2*DSTATE
#define DFFN    2048
#define BETA    0.5f
#define CHUNK   128
#define NCHUNK  8

// ---------------- scratch (device globals; no runtime allocation) ----------
__device__ float g_zxbcdt[NTOK*DINPROJ];
__device__ float g_xc0[NTOK*CONVDIM];
__device__ float g_xc1[NTOK*CONVDIM];
__device__ float g_dt [NTOK*NHEADS];
__device__ float g_y0 [NTOK*DINNER];
__device__ float g_y1 [NTOK*DINNER];
__device__ float g_G  [NTOK*DINNER];
__device__ float g_O  [NTOK*DMODEL];
__device__ float g_Xln[NTOK*DMODEL];
__device__ float g_H1 [NTOK*DFFN];
__device__ float g_H2 [NTOK*DMODEL];
// chunked-scan scratch
__device__ float g_cum[2*BATCH*NHEADS*SEQLEN];
__device__ float g_L  [2*BATCH*NHEADS*NCHUNK*HEADDIM*DSTATE];
__device__ float g_Hi [2*BATCH*NHEADS*NCHUNK*HEADDIM*DSTATE];

// ---------------- helpers ---------------------------------------------------
__device__ __forceinline__ float siluf(float v) { return v / (1.0f + expf(-v)); }
__device__ __forceinline__ float geluf(float v) { return 0.5f * v * (1.0f + erff(v * 0.70710678118654752f)); }
__device__ __forceinline__ float softplusf(float x) { return fmaxf(x, 0.0f) + log1pf(expf(-fabsf(x))); }
__device__ __forceinline__ uint32_t f2tf32(float x) {
    uint32_t r; asm("cvt.rna.tf32.f32 %0, %1;" : "=r"(r) : "f"(x)); return r;
}

__device__ __forceinline__ float blockReduceSum(float v, float* sdata) {
    int tid = threadIdx.x;
    sdata[tid] = v; __syncthreads();
    for (int s = blockDim.x >> 1; s > 0; s >>= 1) {
        if (tid < s) sdata[tid] += sdata[tid + s];
        __syncthreads();
    }
    float r = sdata[0]; __syncthreads();
    return r;
}

// ---------------- TF32 GEMM v2: C[M,N] = A[M,K] @ B[N,K]^T ------------------
// 128x128x16 tile, 256 threads (8 warps 2x4), warp tile 64x32 via m16n8k8.
// Double-buffered smem + register prefetch. EPI: 0 none, 1 +bias, 2 gelu(+bias)
#define LDS_ 20   // padded smem row stride (floats)

template<int EPI>
__global__ __launch_bounds__(256, 2)
void tf32gemm(const float* __restrict__ A, const float* __restrict__ B,
              const float* __restrict__ bias, float* __restrict__ C,
              int M, int N, int K)
{
    __shared__ float As[2][128 * LDS_];
    __shared__ float Bs[2][128 * LDS_];

    const int tid = threadIdx.x;
    const int m0 = blockIdx.y * 128;
    const int n0 = blockIdx.x * 128;

    const int w    = tid >> 5;
    const int lane = tid & 31;
    const int wm   = (w >> 2) * 64;
    const int wn   = (w & 3) * 32;
    const int gr   = lane >> 2;
    const int gc   = lane & 3;

    // global load mapping: 128x16 tile = 512 float4; thread loads rows r and r+64
    const int lrow = tid >> 2;          // 0..63
    const int lk   = (tid & 3) * 4;     // 0,4,8,12

    const float* Ap0 = A + (size_t)(m0 + lrow) * K + lk;
    const float* Ap1 = A + (size_t)(m0 + lrow + 64) * K + lk;
    const int br0 = n0 + lrow, br1 = n0 + lrow + 64;
    const bool ok0 = br0 < N, ok1 = br1 < N;
    const float* Bp0 = B + (size_t)(ok0 ? br0 : 0) * K + lk;
    const float* Bp1 = B + (size_t)(ok1 ? br1 : 0) * K + lk;

    float acc[4][4][4];
    #pragma unroll
    for (int i = 0; i < 4; ++i)
        #pragma unroll
        for (int j = 0; j < 4; ++j)
            #pragma unroll
            for (int r = 0; r < 4; ++r) acc[i][j][r] = 0.0f;

    const int KT = K / 16;

    // prologue: tile 0 -> buffer 0
    {
        float4 a0 = *(const float4*)Ap0;
        float4 a1 = *(const float4*)Ap1;
        float4 b0 = ok0 ? *(const float4*)Bp0 : make_float4(0,0,0,0);
        float4 b1 = ok1 ? *(const float4*)Bp1 : make_float4(0,0,0,0);
        float* as = &As[0][lrow * LDS_ + lk];
        as[0]=__uint_as_float(f2tf32(a0.x)); as[1]=__uint_as_float(f2tf32(a0.y));
        as[2]=__uint_as_float(f2tf32(a0.z)); as[3]=__uint_as_float(f2tf32(a0.w));
        as += 64 * LDS_;
        as[0]=__uint_as_float(f2tf32(a1.x)); as[1]=__uint_as_float(f2tf32(a1.y));
        as[2]=__uint_as_float(f2tf32(a1.z)); as[3]=__uint_as_float(f2tf32(a1.w));
        float* bs = &Bs[0][lrow * LDS_ + lk];
        bs[0]=__uint_as_float(f2tf32(b0.x)); bs[1]=__uint_as_float(f2tf32(b0.y));
        bs[2]=__uint_as_float(f2tf32(b0.z)); bs[3]=__uint_as_float(f2tf32(b0.w));
        bs += 64 * LDS_;
        bs[0]=__uint_as_float(f2tf32(b1.x)); bs[1]=__uint_as_float(f2tf32(b1.y));
        bs[2]=__uint_as_float(f2tf32(b1.z)); bs[3]=__uint_as_float(f2tf32(b1.w));
    }
    __syncthreads();

    for (int kt = 0; kt < KT; ++kt) {
        const int cur = kt & 1;
        float4 pa0, pa1, pb0, pb1;
        const bool more = (kt + 1 < KT);
        if (more) {
            size_t off = (size_t)(kt + 1) * 16;
            pa0 = *(const float4*)(Ap0 + off);
            pa1 = *(const float4*)(Ap1 + off);
            pb0 = ok0 ? *(const float4*)(Bp0 + off) : make_float4(0,0,0,0);
            pb1 = ok1 ? *(const float4*)(Bp1 + off) : make_float4(0,0,0,0);
        }

        #pragma unroll
        for (int kk = 0; kk < 2; ++kk) {
            const int k0 = kk * 8;
            uint32_t af[4][4];
            #pragma unroll
            for (int mi = 0; mi < 4; ++mi) {
                int r = wm + mi * 16 + gr;
                af[mi][0] = __float_as_uint(As[cur][r * LDS_ + k0 + gc]);
                af[mi][1] = __float_as_uint(As[cur][(r + 8) * LDS_ + k0 + gc]);
                af[mi][2] = __float_as_uint(As[cur][r * LDS_ + k0 + gc + 4]);
                af[mi][3] = __float_as_uint(As[cur][(r + 8) * LDS_ + k0 + gc + 4]);
            }
            uint32_t bf[4][2];
            #pragma unroll
            for (int ni = 0; ni < 4; ++ni) {
                int c = wn + ni * 8 + gr;
                bf[ni][0] = __float_as_uint(Bs[cur][c * LDS_ + k0 + gc]);
                bf[ni][1] = __float_as_uint(Bs[cur][c * LDS_ + k0 + gc + 4]);
            }
            #pragma unroll
            for (int mi = 0; mi < 4; ++mi)
                #pragma unroll
                for (int ni = 0; ni < 4; ++ni) {
                    asm volatile(
                        "mma.sync.aligned.m16n8k8.row.col.f32.tf32.tf32.f32 "
                        "{%0,%1,%2,%3}, {%4,%5,%6,%7}, {%8,%9}, {%0,%1,%2,%3};"
                        : "+f"(acc[mi][ni][0]), "+f"(acc[mi][ni][1]),
                          "+f"(acc[mi][ni][2]), "+f"(acc[mi][ni][3])
                        : "r"(af[mi][0]), "r"(af[mi][1]), "r"(af[mi][2]), "r"(af[mi][3]),
                          "r"(bf[ni][0]), "r"(bf[ni][1]));
                }
        }

        if (more) {
            const int nxt = cur ^ 1;
            float* as = &As[nxt][lrow * LDS_ + lk];
            as[0]=__uint_as_float(f2tf32(pa0.x)); as[1]=__uint_as_float(f2tf32(pa0.y));
            as[2]=__uint_as_float(f2tf32(pa0.z)); as[3]=__uint_as_float(f2tf32(pa0.w));
            as += 64 * LDS_;
            as[0]=__uint_as_float(f2tf32(pa1.x)); as[1]=__uint_as_float(f2tf32(pa1.y));
            as[2]=__uint_as_float(f2tf32(pa1.z)); as[3]=__uint_as_float(f2tf32(pa1.w));
            float* bs = &Bs[nxt][lrow * LDS_ + lk];
            bs[0]=__uint_as_float(f2tf32(pb0.x)); bs[1]=__uint_as_float(f2tf32(pb0.y));
            bs[2]=__uint_as_float(f2tf32(pb0.z)); bs[3]=__uint_as_float(f2tf32(pb0.w));
            bs += 64 * LDS_;
            bs[0]=__uint_as_float(f2tf32(pb1.x)); bs[1]=__uint_as_float(f2tf32(pb1.y));
            bs[2]=__uint_as_float(f2tf32(pb1.z)); bs[3]=__uint_as_float(f2tf32(pb1.w));
            __syncthreads();
        }
    }

    // epilogue
    #pragma unroll
    for (int mi = 0; mi < 4; ++mi) {
        int r = m0 + wm + mi * 16 + gr;
        #pragma unroll
        for (int ni = 0; ni < 4; ++ni) {
            int cb = n0 + wn + ni * 8 + 2 * gc;
            #pragma unroll
            for (int half = 0; half < 2; ++half) {
                int rr = r + half * 8;
                float v0 = acc[mi][ni][half * 2 + 0];
                float v1 = acc[mi][ni][half * 2 + 1];
                if (cb < N) {
                    if (EPI >= 1) v0 += bias[cb];
                    if (EPI == 2) v0 = geluf(v0);
                    C[(size_t)rr * N + cb] = v0;
                }
                if (cb + 1 < N) {
                    if (EPI >= 1) v1 += bias[cb + 1];
                    if (EPI == 2) v1 = geluf(v1);
                    C[(size_t)rr * N + cb + 1] = v1;
                }
            }
        }
    }
}

// ---------------- conv (causal depthwise, width 4) + silu, both dirs --------
// float4 per thread (4 channels)
__global__ void conv_silu_kernel(const float* __restrict__ conv_w,
                                 const float* __restrict__ conv_b)
{
    int e = blockIdx.x * blockDim.x + threadIdx.x;
    const int C4 = CONVDIM / 4;                      // 288
    const int total = 2 * NTOK * C4;
    if (e >= total) return;
    int dir = e / (NTOK * C4);
    int rem = e - dir * (NTOK * C4);
    int bt = rem / C4;
    int c4 = rem % C4;
    int b = bt / SEQLEN;
    int t = bt % SEQLEN;
    int c = c4 * 4;

    float4 w0 = *(const float4*)&conv_w[(c + 0) * 4];
    float4 w1 = *(const float4*)&conv_w[(c + 1) * 4];
    float4 w2 = *(const float4*)&conv_w[(c + 2) * 4];
    float4 w3 = *(const float4*)&conv_w[(c + 3) * 4];
    float4 acc = *(const float4*)&conv_b[c];

    float wt0[4] = {w0.x, w0.y, w0.z, w0.w};
    float wt1[4] = {w1.x, w1.y, w1.z, w1.w};
    float wt2[4] = {w2.x, w2.y, w2.z, w2.w};
    float wt3[4] = {w3.x, w3.y, w3.z, w3.w};

    #pragma unroll
    for (int k = 0; k < 4; ++k) {
        int tp = t - 3 + k;
        if (tp >= 0) {
            int s = dir ? (SEQLEN - 1 - tp) : tp;
            float4 v = *(const float4*)&g_zxbcdt[(size_t)(b * SEQLEN + s) * DINPROJ + DINNER + c];
            acc.x = fmaf(wt0[k], v.x, acc.x);
            acc.y = fmaf(wt1[k], v.y, acc.y);
            acc.z = fmaf(wt2[k], v.z, acc.z);
            acc.w = fmaf(wt3[k], v.w, acc.w);
        }
    }
    acc.x = siluf(acc.x); acc.y = siluf(acc.y);
    acc.z = siluf(acc.z); acc.w = siluf(acc.w);
    float* out = dir ? g_xc1 : g_xc0;
    *(float4*)&out[(size_t)bt * CONVDIM + c] = acc;
}

// ---------------- dt = softplus(raw + bias) ---------------------------------
__global__ void dt_kernel(const float* __restrict__ dt_bias)
{
    int e = blockIdx.x * blockDim.x + threadIdx.x;
    if (e >= NTOK * NHEADS) return;
    int bt = e / NHEADS;
    int h  = e % NHEADS;
    float x = g_zxbcdt[(size_t)bt * DINPROJ + (DINNER + CONVDIM) + h] + dt_bias[h];
    g_dt[e] = softplusf(x);
}

// ---------------- SSD pass A: chunk-local scans (pipelined) ------------------
// 4096 blocks: (dir, b, h, chunk, half). 32 threads.
__global__ __launch_bounds__(32)
void ssd_local_kernel(const float* __restrict__ A_log,
                      const float* __restrict__ Dp)
{
    int blk   = blockIdx.x;
    int half  = blk & 1;
    int chunk = (blk >> 1) & 7;
    int h     = (blk >> 4) & 15;
    int b     = (blk >> 8) & 7;
    int dir   = blk >> 11;
    int lane  = threadIdx.x;
    int p     = half * 32 + lane;

    const float* xc = dir ? g_xc1 : g_xc0;
    float* yout = dir ? g_y1 : g_y0;

    float A  = -expf(A_log[h]);
    float Dh = Dp[h];

    float st[64];
    #pragma unroll
    for (int n = 0; n < 64; ++n) st[n] = 0.0f;

    __shared__ float4 sBC[2][32];

    const size_t hb = (size_t)(dir * BATCH + b) * NHEADS + h;
    const int t0 = chunk * CHUNK;
    float cum = 1.0f;

    // prologue: stage step 0
    {
        size_t base0 = (size_t)(b * SEQLEN + t0) * CONVDIM;
        sBC[0][lane] = *(const float4*)&xc[base0 + DINNER + lane * 4];
    }
    float xv;
    float dtv;
    {
        size_t base0 = (size_t)(b * SEQLEN + t0) * CONVDIM;
        xv = xc[base0 + h * HEADDIM + p];
        int s0 = dir ? (SEQLEN - 1 - t0) : t0;
        dtv = g_dt[(size_t)(b * SEQLEN + s0) * NHEADS + h];
    }
    __syncwarp();

    for (int tl = 0; tl < CHUNK; ++tl) {
        const int cur = tl & 1;
        const int t = t0 + tl;

        // prefetch next step
        float4 nbc = make_float4(0,0,0,0);
        float nx = 0.f, ndt = 0.f;
        if (tl + 1 < CHUNK) {
            size_t baseN = (size_t)(b * SEQLEN + t + 1) * CONVDIM;
            nbc = *(const float4*)&xc[baseN + DINNER + lane * 4];
            nx  = xc[baseN + h * HEADDIM + p];
            int sn = dir ? (SEQLEN - 2 - t) : (t + 1);
            ndt = g_dt[(size_t)(b * SEQLEN + sn) * NHEADS + h];
        }

        float dA = expf(dtv * A);
        cum *= dA;
        if (half == 0 && lane == 0) g_cum[hb * SEQLEN + t] = cum;

        float coef = dtv * xv;
        float a0 = 0.f, a1 = 0.f, a2 = 0.f, a3 = 0.f;
        #pragma unroll
        for (int q = 0; q < 16; ++q) {
            float4 Bv = sBC[cur][q];
            float4 Cv = sBC[cur][16 + q];
            st[q*4+0] = fmaf(st[q*4+0], dA, coef * Bv.x); a0 = fmaf(st[q*4+0], Cv.x, a0);
            st[q*4+1] = fmaf(st[q*4+1], dA, coef * Bv.y); a1 = fmaf(st[q*4+1], Cv.y, a1);
            st[q*4+2] = fmaf(st[q*4+2], dA, coef * Bv.z); a2 = fmaf(st[q*4+2], Cv.z, a2);
            st[q*4+3] = fmaf(st[q*4+3], dA, coef * Bv.w); a3 = fmaf(st[q*4+3], Cv.w, a3);
        }
        yout[(size_t)(b * SEQLEN + t) * DINNER + h * HEADDIM + p] =
            (a0 + a1) + (a2 + a3) + xv * Dh;

        if (tl + 1 < CHUNK) {
            sBC[cur ^ 1][lane] = nbc;
            xv  = nx;
            dtv = ndt;
        }
        __syncwarp();
    }

    size_t lb = ((hb * NCHUNK) + chunk) * (HEADDIM * DSTATE) + (size_t)p * DSTATE;
    #pragma unroll
    for (int q = 0; q < 16; ++q)
        *(float4*)&g_L[lb + q * 4] = make_float4(st[q*4], st[q*4+1], st[q*4+2], st[q*4+3]);
}

// ---------------- SSD pass B: sequential chunk-state combine -----------------
__global__ __launch_bounds__(64)
void ssd_combine_kernel()
{
    int blk = blockIdx.x;
    int h   = blk & 15;
    int b   = (blk >> 4) & 7;
    int dir = blk >> 7;
    int p   = threadIdx.x;

    const size_t hb = (size_t)(dir * BATCH + b) * NHEADS + h;

    float H[64];
    #pragma unroll
    for (int n = 0; n < 64; ++n) H[n] = 0.0f;

    for (int c = 0; c < NCHUNK; ++c) {
        size_t off = ((hb * NCHUNK) + c) * (HEADDIM * DSTATE) + (size_t)p * DSTATE;
        #pragma unroll
        for (int q = 0; q < 16; ++q)
            *(float4*)&g_Hi[off + q * 4] = make_float4(H[q*4], H[q*4+1], H[q*4+2], H[q*4+3]);
        if (c < NCHUNK - 1) {
            float P = g_cum[hb * SEQLEN + c * CHUNK + CHUNK - 1];
            #pragma unroll
            for (int q = 0; q < 16; ++q) {
                float4 L = *(const float4*)&g_L[off + q * 4];
                H[q*4+0] = fmaf(H[q*4+0], P, L.x);
                H[q*4+1] = fmaf(H[q*4+1], P, L.y);
                H[q*4+2] = fmaf(H[q*4+2], P, L.z);
                H[q*4+3] = fmaf(H[q*4+3], P, L.w);
            }
        }
    }
}

// ---------------- SSD pass C: fixup with chunk-initial state (pipelined) -----
// 3584 blocks: (dir,b,h, chunk 1..7, half). y += cum_t * (C_t . Hinit[p,:])
__global__ __launch_bounds__(32)
void ssd_fixup_kernel()
{
    int blk  = blockIdx.x;
    int half = blk & 1;
    int idx  = blk >> 1;
    int chunk = (idx % 7) + 1;
    idx /= 7;
    int h   = idx & 15;
    int b   = (idx >> 4) & 7;
    int dir = idx >> 7;
    int lane = threadIdx.x;
    int p    = half * 32 + lane;

    const float* xc = dir ? g_xc1 : g_xc0;
    float* yout = dir ? g_y1 : g_y0;
    const size_t hb = (size_t)(dir * BATCH + b) * NHEADS + h;

    float H[64];
    {
        size_t off = ((hb * NCHUNK) + chunk) * (HEADDIM * DSTATE) + (size_t)p * DSTATE;
        #pragma unroll
        for (int q = 0; q < 16; ++q) {
            float4 v = *(const float4*)&g_Hi[off + q * 4];
            H[q*4] = v.x; H[q*4+1] = v.y; H[q*4+2] = v.z; H[q*4+3] = v.w;
        }
    }

    __shared__ float4 sC[2][16];
    const int t0 = chunk * CHUNK;

    // prologue
    if (lane < 16) {
        size_t base0 = (size_t)(b * SEQLEN + t0) * CONVDIM;
        sC[0][lane] = *(const float4*)&xc[base0 + DINNER + DSTATE + lane * 4];
    }
    float cumv = g_cum[hb * SEQLEN + t0];
    __syncwarp();

    for (int tl = 0; tl < CHUNK; ++tl) {
        const int cur = tl & 1;
        const int t = t0 + tl;
        int tok = b * SEQLEN + t;

        float4 nC = make_float4(0,0,0,0);
        float ncum = 0.f;
        if (tl + 1 < CHUNK) {
            if (lane < 16) {
                size_t baseN = (size_t)(tok + 1) * CONVDIM;
                nC = *(const float4*)&xc[baseN + DINNER + DSTATE + lane * 4];
            }
            ncum = g_cum[hb * SEQLEN + t + 1];
        }

        float a0 = 0.f, a1 = 0.f, a2 = 0.f, a3 = 0.f;
        #pragma unroll
        for (int q = 0; q < 16; ++q) {
            float4 Cv = sC[cur][q];
            a0 = fmaf(H[q*4+0], Cv.x, a0);
            a1 = fmaf(H[q*4+1], Cv.y, a1);
            a2 = fmaf(H[q*4+2], Cv.z, a2);
            a3 = fmaf(H[q*4+3], Cv.w, a3);
        }
        size_t yi = (size_t)tok * DINNER + h * HEADDIM + p;
        yout[yi] = fmaf(cumv, (a0 + a1) + (a2 + a3), yout[yi]);

        if (tl + 1 < CHUNK) {
            if (lane < 16) sC[cur ^ 1][lane] = nC;
            cumv = ncum;
        }
        __syncwarp();
    }
}

// ---------------- gate (y * silu(z)), RMS norm, combine fwd+beta*bwd --------
__global__ __launch_bounds__(256)
void gate_rms_combine_kernel(const float* __restrict__ norm_w)
{
    __shared__ float sdata[256];
    int bt = blockIdx.x;
    int b = bt / SEQLEN;
    int t = bt % SEQLEN;
    int tid = threadIdx.x;

    float gf[4], gb[4];
    float ssf = 0.0f, ssb = 0.0f;
    size_t zf = (size_t)bt * DINPROJ;
    size_t zb = (size_t)(b * SEQLEN + (SEQLEN - 1 - t)) * DINPROJ;
    #pragma unroll
    for (int i = 0; i < 4; ++i) {
        int j = tid + i * 256;
        float yv = g_y0[(size_t)bt * DINNER + j];
        float zv = g_zxbcdt[zf + j];
        gf[i] = yv * siluf(zv);
        ssf = fmaf(gf[i], gf[i], ssf);

        float yv2 = g_y1[(size_t)bt * DINNER + j];
        float zv2 = g_zxbcdt[zb + j];
        gb[i] = yv2 * siluf(zv2);
        ssb = fmaf(gb[i], gb[i], ssb);
    }
    float sumf = blockReduceSum(ssf, sdata);
    float sumb = blockReduceSum(ssb, sdata);
    float rf = rsqrtf(sumf / DINNER + 1e-5f);
    float rb = rsqrtf(sumb / DINNER + 1e-5f);

    #pragma unroll
    for (int i = 0; i < 4; ++i) {
        int j = tid + i * 256;
        g_G[(size_t)bt * DINNER + j] = (gf[i] * rf + BETA * gb[i] * rb) * norm_w[j];
    }
}

// ---------------- LN1: h = layernorm(O + item_emb) --------------------------
__global__ __launch_bounds__(256)
void ln1_kernel(const float* __restrict__ emb,
                const float* __restrict__ w, const float* __restrict__ bln)
{
    __shared__ float sdata[256];
    int bt = blockIdx.x;
    int tid = threadIdx.x;
    size_t base = (size_t)bt * DMODEL;

    float v[2], s = 0.0f, sq = 0.0f;
    #pragma unroll
    for (int i = 0; i < 2; ++i) {
        int j = tid + i * 256;
        v[i] = g_O[base + j] + emb[base + j];
        s += v[i];
        sq = fmaf(v[i], v[i], sq);
    }
    float sum = blockReduceSum(s, sdata);
    float sumsq = blockReduceSum(sq, sdata);
    float mu = sum / DMODEL;
    float var = sumsq / DMODEL - mu * mu;
    float rs = rsqrtf(var + 1e-12f);
    #pragma unroll
    for (int i = 0; i < 2; ++i) {
        int j = tid + i * 256;
        g_Xln[base + j] = (v[i] - mu) * rs * w[j] + bln[j];
    }
}

// ---------------- LN2: out = layernorm(H2 + Xln) ----------------------------
__global__ __launch_bounds__(256)
void ln2_kernel(float* __restrict__ out,
                const float* __restrict__ w, const float* __restrict__ bln)
{
    __shared__ float sdata[256];
    int bt = blockIdx.x;
    int tid = threadIdx.x;
    size_t base = (size_t)bt * DMODEL;

    float v[2], s = 0.0f, sq = 0.0f;
    #pragma unroll
    for (int i = 0; i < 2; ++i) {
        int j = tid + i * 256;
        v[i] = g_H2[base + j] + g_Xln[base + j];
        s += v[i];
        sq = fmaf(v[i], v[i], sq);
    }
    float sum = blockReduceSum(s, sdata);
    float sumsq = blockReduceSum(sq, sdata);
    float mu = sum / DMODEL;
    float var = sumsq / DMODEL - mu * mu;
    float rs = rsqrtf(var + 1e-12f);
    #pragma unroll
    for (int i = 0; i < 2; ++i) {
        int j = tid + i * 256;
        out[base + j] = (v[i] - mu) * rs * w[j] + bln[j];
    }
}

// ---------------- launch -----------------------------------------------------
extern "C" void kernel_launch(void* const* d_in, const int* in_sizes, int n_in,
                              void* d_out, int out_size)
{
    const float* item_emb   = (const float*)d_in[0];
    const float* in_proj_w  = (const float*)d_in[3];
    const float* conv_w     = (const float*)d_in[4];
    const float* conv_b     = (const float*)d_in[5];
    const float* dt_bias    = (const float*)d_in[6];
    const float* A_log      = (const float*)d_in[7];
    const float* Dp         = (const float*)d_in[8];
    const float* norm_w     = (const float*)d_in[9];
    const float* out_proj_w = (const float*)d_in[10];
    const float* ln_w       = (const float*)d_in[11];
    const float* ln_b       = (const float*)d_in[12];
    const float* ffn_w1     = (const float*)d_in[13];
    const float* ffn_b1     = (const float*)d_in[14];
    const float* ffn_w2     = (const float*)d_in[15];
    const float* ffn_b2     = (const float*)d_in[16];
    const float* ffn_ln_w   = (const float*)d_in[17];
    const float* ffn_ln_b   = (const float*)d_in[18];
    float* out = (float*)d_out;

    float *p_zx, *p_G, *p_O, *p_Xln, *p_H1, *p_H2;
    cudaGetSymbolAddress((void**)&p_zx,  g_zxbcdt);
    cudaGetSymbolAddress((void**)&p_G,   g_G);
    cudaGetSymbolAddress((void**)&p_O,   g_O);
    cudaGetSymbolAddress((void**)&p_Xln, g_Xln);
    cudaGetSymbolAddress((void**)&p_H1,  g_H1);
    cudaGetSymbolAddress((void**)&p_H2,  g_H2);

    // 1) in_proj (8192 x 2192 x 512)
    {
        dim3 grid((DINPROJ + 127) / 128, NTOK / 128);
        tf32gemm<0><<<grid, 256>>>(item_emb, in_proj_w, nullptr, p_zx, NTOK, DINPROJ, DMODEL);
    }

    // 2) conv + silu (float4)
    {
        int total = 2 * NTOK * (CONVDIM / 4);
        conv_silu_kernel<<<(total + 255) / 256, 256>>>(conv_w, conv_b);
    }

    // 3) dt softplus
    {
        int total = NTOK * NHEADS;
        dt_kernel<<<(total + 255) / 256, 256>>>(dt_bias);
    }

    // 4) SSD
    ssd_local_kernel<<<4096, 32>>>(A_log, Dp);
    ssd_combine_kernel<<<256, 64>>>();
    ssd_fixup_kernel<<<3584, 32>>>();

    // 5) gate + RMS + combine
    gate_rms_combine_kernel<<<NTOK, 256>>>(norm_w);

    // 6) out_proj (8192 x 512 x 1024)
    {
        dim3 grid(DMODEL / 128, NTOK / 128);
        tf32gemm<0><<<grid, 256>>>(p_G, out_proj_w, nullptr, p_O, NTOK, DMODEL, DINNER);
    }

    // 7) LN1
    ln1_kernel<<<NTOK, 256>>>(item_emb, ln_w, ln_b);

    // 8) FFN1 (8192 x 2048 x 512)
    {
        dim3 grid(DFFN / 128, NTOK / 128);
        tf32gemm<2><<<grid, 256>>>(p_Xln, ffn_w1, ffn_b1, p_H1, NTOK, DFFN, DMODEL);
    }

    // 9) FFN2 (8192 x 512 x 2048)
    {
        dim3 grid(DMODEL / 128, NTOK / 128);
        tf32gemm<1><<<grid, 256>>>(p_H1, ffn_w2, ffn_b2, p_H2, NTOK, DMODEL, DFFN);
    }

    // 10) final LN
    ln2_kernel<<<NTOK, 256>>>(out, ffn_ln_w, ffn_ln_b);
}

// round 5
// speedup vs baseline: 1.2908x; 1.2908x over previous
#include <cuda_runtime.h>
#include <cuda_fp16.h>
#include <math.h>
#include <stdint.h>

#define BATCH   8
#define SEQLEN  1024
#define NTOK    (BATCH*SEQLEN)     // 8192
#define DMODEL  512
#define DSTATE  64
#define DINNER  1024
#define NHEADS  16
#define HEADDIM 64
#define DINPROJ 2192
#define CONVDIM 1152
#define DFFN    2048
#define BETA    0.5f
#define CHUNK   256
#define NCHUNK  4

// ---------------- scratch ----------------------------------------------------
__device__ float g_zxbcdt[NTOK*DINPROJ];
__device__ float g_xc0[NTOK*CONVDIM];
__device__ float g_xc1[NTOK*CONVDIM];
__device__ float g_dt [NTOK*NHEADS];
__device__ float g_y0 [NTOK*DINNER];
__device__ float g_y1 [NTOK*DINNER];
__device__ float g_G  [NTOK*DINNER];
__device__ float g_O  [NTOK*DMODEL];
__device__ float g_Xln[NTOK*DMODEL];
__device__ float g_H1 [NTOK*DFFN];
__device__ float g_H2 [NTOK*DMODEL];
__device__ float g_cum[2*BATCH*NHEADS*SEQLEN];
__device__ float g_L  [2*BATCH*NHEADS*NCHUNK*HEADDIM*DSTATE];
__device__ float g_Hi [2*BATCH*NHEADS*NCHUNK*HEADDIM*DSTATE];

// ---------------- helpers ----------------------------------------------------
__device__ __forceinline__ float siluf(float v) { return v / (1.0f + expf(-v)); }
__device__ __forceinline__ float geluf(float v) { return 0.5f * v * (1.0f + erff(v * 0.70710678118654752f)); }
__device__ __forceinline__ float softplusf(float x) { return fmaxf(x, 0.0f) + log1pf(expf(-fabsf(x))); }
__device__ __forceinline__ uint32_t pack2h(float x, float y) {
    __half2 h = __float22half2_rn(make_float2(x, y));
    return *(uint32_t*)&h;
}

__device__ __forceinline__ float blockReduceSum(float v, float* sdata) {
    int tid = threadIdx.x;
    sdata[tid] = v; __syncthreads();
    for (int s = blockDim.x >> 1; s > 0; s >>= 1) {
        if (tid < s) sdata[tid] += sdata[tid + s];
        __syncthreads();
    }
    float r = sdata[0]; __syncthreads();
    return r;
}

// ---------------- FP16 GEMM: C[M,N] = A[M,K] @ B[N,K]^T ---------------------
// 128x128x32 tile, 256 threads (8 warps 2x4), warp tile 64x32 via m16n8k16.
// Double-buffered smem (half), prefetch converted to half2 at load time.
// EPI: 0 none, 1 +bias, 2 gelu(+bias)
#define LDH 20   // uint32 (half2 pairs) per smem row: 40 halves (32 data + 8 pad)

template<int EPI>
__global__ __launch_bounds__(256, 2)
void h16gemm(const float* __restrict__ A, const float* __restrict__ B,
             const float* __restrict__ bias, float* __restrict__ C,
             int M, int N, int K)
{
    __shared__ uint32_t As[2][128 * LDH];
    __shared__ uint32_t Bs[2][128 * LDH];

    const int tid = threadIdx.x;
    const int m0 = blockIdx.y * 128;
    const int n0 = blockIdx.x * 128;

    const int w    = tid >> 5;
    const int lane = tid & 31;
    const int wm   = (w >> 2) * 64;
    const int wn   = (w & 3) * 32;
    const int gr   = lane >> 2;       // 0..7
    const int gcw  = lane & 3;        // word (half2) column 0..3

    // global load mapping: 4 iterations, each thread one float4 of A and B
    const int lrow = tid >> 3;        // 0..31 (+32*i)
    const int lkq  = (tid & 7) * 4;   // 0..28

    float acc[4][4][4];
    #pragma unroll
    for (int i = 0; i < 4; ++i)
        #pragma unroll
        for (int j = 0; j < 4; ++j)
            #pragma unroll
            for (int r = 0; r < 4; ++r) acc[i][j][r] = 0.0f;

    const int KT = K / 32;

    // prologue: tile 0 -> buffer 0
    #pragma unroll
    for (int i = 0; i < 4; ++i) {
        int row = lrow + i * 32;
        float4 a = *(const float4*)&A[(size_t)(m0 + row) * K + lkq];
        As[0][row * LDH + lkq / 2 + 0] = pack2h(a.x, a.y);
        As[0][row * LDH + lkq / 2 + 1] = pack2h(a.z, a.w);
        int brow = n0 + row;
        float4 b = (brow < N) ? *(const float4*)&B[(size_t)brow * K + lkq]
                              : make_float4(0.f, 0.f, 0.f, 0.f);
        Bs[0][row * LDH + lkq / 2 + 0] = pack2h(b.x, b.y);
        Bs[0][row * LDH + lkq / 2 + 1] = pack2h(b.z, b.w);
    }
    __syncthreads();

    for (int kt = 0; kt < KT; ++kt) {
        const int cur = kt & 1;
        const bool more = (kt + 1 < KT);

        // prefetch next tile, converting to half2 immediately (16 regs)
        uint32_t pa[4][2], pb[4][2];
        if (more) {
            size_t koff = (size_t)(kt + 1) * 32 + lkq;
            #pragma unroll
            for (int i = 0; i < 4; ++i) {
                int row = lrow + i * 32;
                float4 a = *(const float4*)&A[(size_t)(m0 + row) * K + koff];
                pa[i][0] = pack2h(a.x, a.y);
                pa[i][1] = pack2h(a.z, a.w);
                int brow = n0 + row;
                float4 b = (brow < N) ? *(const float4*)&B[(size_t)brow * K + koff]
                                      : make_float4(0.f, 0.f, 0.f, 0.f);
                pb[i][0] = pack2h(b.x, b.y);
                pb[i][1] = pack2h(b.z, b.w);
            }
        }

        #pragma unroll
        for (int kk = 0; kk < 2; ++kk) {
            const int kw = kk * 8;   // word offset (16 halves)
            uint32_t af[4][4];
            #pragma unroll
            for (int mi = 0; mi < 4; ++mi) {
                int r = wm + mi * 16 + gr;
                af[mi][0] = As[cur][r * LDH + kw + gcw];
                af[mi][1] = As[cur][(r + 8) * LDH + kw + gcw];
                af[mi][2] = As[cur][r * LDH + kw + gcw + 4];
                af[mi][3] = As[cur][(r + 8) * LDH + kw + gcw + 4];
            }
            uint32_t bf[4][2];
            #pragma unroll
            for (int ni = 0; ni < 4; ++ni) {
                int c = wn + ni * 8 + gr;
                bf[ni][0] = Bs[cur][c * LDH + kw + gcw];
                bf[ni][1] = Bs[cur][c * LDH + kw + gcw + 4];
            }
            #pragma unroll
            for (int mi = 0; mi < 4; ++mi)
                #pragma unroll
                for (int ni = 0; ni < 4; ++ni) {
                    asm volatile(
                        "mma.sync.aligned.m16n8k16.row.col.f32.f16.f16.f32 "
                        "{%0,%1,%2,%3}, {%4,%5,%6,%7}, {%8,%9}, {%0,%1,%2,%3};"
                        : "+f"(acc[mi][ni][0]), "+f"(acc[mi][ni][1]),
                          "+f"(acc[mi][ni][2]), "+f"(acc[mi][ni][3])
                        : "r"(af[mi][0]), "r"(af[mi][1]), "r"(af[mi][2]), "r"(af[mi][3]),
                          "r"(bf[ni][0]), "r"(bf[ni][1]));
                }
        }

        if (more) {
            const int nxt = cur ^ 1;
            #pragma unroll
            for (int i = 0; i < 4; ++i) {
                int row = lrow + i * 32;
                As[nxt][row * LDH + lkq / 2 + 0] = pa[i][0];
                As[nxt][row * LDH + lkq / 2 + 1] = pa[i][1];
                Bs[nxt][row * LDH + lkq / 2 + 0] = pb[i][0];
                Bs[nxt][row * LDH + lkq / 2 + 1] = pb[i][1];
            }
            __syncthreads();
        }
    }

    // epilogue (same fragment layout as m16n8k8: c0,c1 row gr, c2,c3 row gr+8)
    #pragma unroll
    for (int mi = 0; mi < 4; ++mi) {
        int r = m0 + wm + mi * 16 + gr;
        #pragma unroll
        for (int ni = 0; ni < 4; ++ni) {
            int cb = n0 + wn + ni * 8 + 2 * gcw;
            #pragma unroll
            for (int half = 0; half < 2; ++half) {
                int rr = r + half * 8;
                float v0 = acc[mi][ni][half * 2 + 0];
                float v1 = acc[mi][ni][half * 2 + 1];
                if (cb < N) {
                    if (EPI >= 1) v0 += bias[cb];
                    if (EPI == 2) v0 = geluf(v0);
                    C[(size_t)rr * N + cb] = v0;
                }
                if (cb + 1 < N) {
                    if (EPI >= 1) v1 += bias[cb + 1];
                    if (EPI == 2) v1 = geluf(v1);
                    C[(size_t)rr * N + cb + 1] = v1;
                }
            }
        }
    }
}

// ---------------- conv (causal depthwise, width 4) + silu, float4 -----------
__global__ void conv_silu_kernel(const float* __restrict__ conv_w,
                                 const float* __restrict__ conv_b)
{
    int e = blockIdx.x * blockDim.x + threadIdx.x;
    const int C4 = CONVDIM / 4;
    const int total = 2 * NTOK * C4;
    if (e >= total) return;
    int dir = e / (NTOK * C4);
    int rem = e - dir * (NTOK * C4);
    int bt = rem / C4;
    int c4 = rem % C4;
    int b = bt / SEQLEN;
    int t = bt % SEQLEN;
    int c = c4 * 4;

    float4 w0 = *(const float4*)&conv_w[(c + 0) * 4];
    float4 w1 = *(const float4*)&conv_w[(c + 1) * 4];
    float4 w2 = *(const float4*)&conv_w[(c + 2) * 4];
    float4 w3 = *(const float4*)&conv_w[(c + 3) * 4];
    float4 acc = *(const float4*)&conv_b[c];

    float wt0[4] = {w0.x, w0.y, w0.z, w0.w};
    float wt1[4] = {w1.x, w1.y, w1.z, w1.w};
    float wt2[4] = {w2.x, w2.y, w2.z, w2.w};
    float wt3[4] = {w3.x, w3.y, w3.z, w3.w};

    #pragma unroll
    for (int k = 0; k < 4; ++k) {
        int tp = t - 3 + k;
        if (tp >= 0) {
            int s = dir ? (SEQLEN - 1 - tp) : tp;
            float4 v = *(const float4*)&g_zxbcdt[(size_t)(b * SEQLEN + s) * DINPROJ + DINNER + c];
            acc.x = fmaf(wt0[k], v.x, acc.x);
            acc.y = fmaf(wt1[k], v.y, acc.y);
            acc.z = fmaf(wt2[k], v.z, acc.z);
            acc.w = fmaf(wt3[k], v.w, acc.w);
        }
    }
    acc.x = siluf(acc.x); acc.y = siluf(acc.y);
    acc.z = siluf(acc.z); acc.w = siluf(acc.w);
    float* out = dir ? g_xc1 : g_xc0;
    *(float4*)&out[(size_t)bt * CONVDIM + c] = acc;
}

// ---------------- dt = softplus(raw + bias) ---------------------------------
__global__ void dt_kernel(const float* __restrict__ dt_bias)
{
    int e = blockIdx.x * blockDim.x + threadIdx.x;
    if (e >= NTOK * NHEADS) return;
    int bt = e / NHEADS;
    int h  = e % NHEADS;
    float x = g_zxbcdt[(size_t)bt * DINPROJ + (DINNER + CONVDIM) + h] + dt_bias[h];
    g_dt[e] = softplusf(x);
}

// ---------------- SSD pass A: chunk-local scans (round-3 version) -----------
__global__ __launch_bounds__(32)
void ssd_local_kernel(const float* __restrict__ A_log,
                      const float* __restrict__ Dp)
{
    int blk   = blockIdx.x;
    int half  = blk & 1;
    int chunk = (blk >> 1) & 3;
    int h     = (blk >> 3) & 15;
    int b     = (blk >> 7) & 7;
    int dir   = blk >> 10;
    int lane  = threadIdx.x;
    int p     = half * 32 + lane;

    const float* xc = dir ? g_xc1 : g_xc0;
    float* yout = dir ? g_y1 : g_y0;

    float A  = -expf(A_log[h]);
    float Dh = Dp[h];

    float st[64];
    #pragma unroll
    for (int n = 0; n < 64; ++n) st[n] = 0.0f;

    __shared__ float4 sBC[32];

    const size_t hb = (size_t)(dir * BATCH + b) * NHEADS + h;
    float cum = 1.0f;
    const int t0 = chunk * CHUNK;

    for (int tl = 0; tl < CHUNK; ++tl) {
        int t = t0 + tl;
        int tok = b * SEQLEN + t;
        size_t base = (size_t)tok * CONVDIM;

        __syncwarp();
        sBC[lane] = *(const float4*)&xc[base + DINNER + lane * 4];
        float xv = xc[base + h * HEADDIM + p];
        int s = dir ? (SEQLEN - 1 - t) : t;
        float dtv = g_dt[(size_t)(b * SEQLEN + s) * NHEADS + h];
        __syncwarp();

        float dA = expf(dtv * A);
        cum *= dA;
        if (half == 0 && lane == 0) g_cum[hb * SEQLEN + t] = cum;

        float coef = dtv * xv;
        float a0 = 0.f, a1 = 0.f, a2 = 0.f, a3 = 0.f;
        #pragma unroll
        for (int q = 0; q < 16; ++q) {
            float4 Bv = sBC[q];
            float4 Cv = sBC[16 + q];
            st[q*4+0] = fmaf(st[q*4+0], dA, coef * Bv.x); a0 = fmaf(st[q*4+0], Cv.x, a0);
            st[q*4+1] = fmaf(st[q*4+1], dA, coef * Bv.y); a1 = fmaf(st[q*4+1], Cv.y, a1);
            st[q*4+2] = fmaf(st[q*4+2], dA, coef * Bv.z); a2 = fmaf(st[q*4+2], Cv.z, a2);
            st[q*4+3] = fmaf(st[q*4+3], dA, coef * Bv.w); a3 = fmaf(st[q*4+3], Cv.w, a3);
        }
        yout[(size_t)tok * DINNER + h * HEADDIM + p] =
            (a0 + a1) + (a2 + a3) + xv * Dh;
    }

    size_t lb = ((hb * NCHUNK) + chunk) * (HEADDIM * DSTATE) + (size_t)p * DSTATE;
    #pragma unroll
    for (int q = 0; q < 16; ++q)
        *(float4*)&g_L[lb + q * 4] = make_float4(st[q*4], st[q*4+1], st[q*4+2], st[q*4+3]);
}

// ---------------- SSD pass B: sequential chunk-state combine -----------------
__global__ __launch_bounds__(64)
void ssd_combine_kernel()
{
    int blk = blockIdx.x;
    int h   = blk & 15;
    int b   = (blk >> 4) & 7;
    int dir = blk >> 7;
    int p   = threadIdx.x;

    const size_t hb = (size_t)(dir * BATCH + b) * NHEADS + h;

    float H[64];
    #pragma unroll
    for (int n = 0; n < 64; ++n) H[n] = 0.0f;

    for (int c = 0; c < NCHUNK; ++c) {
        size_t off = ((hb * NCHUNK) + c) * (HEADDIM * DSTATE) + (size_t)p * DSTATE;
        #pragma unroll
        for (int q = 0; q < 16; ++q)
            *(float4*)&g_Hi[off + q * 4] = make_float4(H[q*4], H[q*4+1], H[q*4+2], H[q*4+3]);
        if (c < NCHUNK - 1) {
            float P = g_cum[hb * SEQLEN + c * CHUNK + CHUNK - 1];
            #pragma unroll
            for (int q = 0; q < 16; ++q) {
                float4 L = *(const float4*)&g_L[off + q * 4];
                H[q*4+0] = fmaf(H[q*4+0], P, L.x);
                H[q*4+1] = fmaf(H[q*4+1], P, L.y);
                H[q*4+2] = fmaf(H[q*4+2], P, L.z);
                H[q*4+3] = fmaf(H[q*4+3], P, L.w);
            }
        }
    }
}

// ---------------- SSD pass C: fixup (round-3 version) ------------------------
__global__ __launch_bounds__(32)
void ssd_fixup_kernel()
{
    int blk  = blockIdx.x;
    int half = blk & 1;
    int idx  = blk >> 1;
    int chunk = (idx % 3) + 1;
    idx /= 3;
    int h   = idx & 15;
    int b   = (idx >> 4) & 7;
    int dir = idx >> 7;
    int lane = threadIdx.x;
    int p    = half * 32 + lane;

    const float* xc = dir ? g_xc1 : g_xc0;
    float* yout = dir ? g_y1 : g_y0;
    const size_t hb = (size_t)(dir * BATCH + b) * NHEADS + h;

    float H[64];
    {
        size_t off = ((hb * NCHUNK) + chunk) * (HEADDIM * DSTATE) + (size_t)p * DSTATE;
        #pragma unroll
        for (int q = 0; q < 16; ++q) {
            float4 v = *(const float4*)&g_Hi[off + q * 4];
            H[q*4] = v.x; H[q*4+1] = v.y; H[q*4+2] = v.z; H[q*4+3] = v.w;
        }
    }

    __shared__ float4 sC[16];
    const int t0 = chunk * CHUNK;

    for (int tl = 0; tl < CHUNK; ++tl) {
        int t = t0 + tl;
        int tok = b * SEQLEN + t;
        size_t base = (size_t)tok * CONVDIM;

        __syncwarp();
        if (lane < 16)
            sC[lane] = *(const float4*)&xc[base + DINNER + DSTATE + lane * 4];
        __syncwarp();

        float cumv = g_cum[hb * SEQLEN + t];
        float a0 = 0.f, a1 = 0.f, a2 = 0.f, a3 = 0.f;
        #pragma unroll
        for (int q = 0; q < 16; ++q) {
            float4 Cv = sC[q];
            a0 = fmaf(H[q*4+0], Cv.x, a0);
            a1 = fmaf(H[q*4+1], Cv.y, a1);
            a2 = fmaf(H[q*4+2], Cv.z, a2);
            a3 = fmaf(H[q*4+3], Cv.w, a3);
        }
        size_t yi = (size_t)tok * DINNER + h * HEADDIM + p;
        yout[yi] = fmaf(cumv, (a0 + a1) + (a2 + a3), yout[yi]);
    }
}

// ---------------- gate + RMS + combine ---------------------------------------
__global__ __launch_bounds__(256)
void gate_rms_combine_kernel(const float* __restrict__ norm_w)
{
    __shared__ float sdata[256];
    int bt = blockIdx.x;
    int b = bt / SEQLEN;
    int t = bt % SEQLEN;
    int tid = threadIdx.x;

    float gf[4], gb[4];
    float ssf = 0.0f, ssb = 0.0f;
    size_t zf = (size_t)bt * DINPROJ;
    size_t zb = (size_t)(b * SEQLEN + (SEQLEN - 1 - t)) * DINPROJ;
    #pragma unroll
    for (int i = 0; i < 4; ++i) {
        int j = tid + i * 256;
        float yv = g_y0[(size_t)bt * DINNER + j];
        float zv = g_zxbcdt[zf + j];
        gf[i] = yv * siluf(zv);
        ssf = fmaf(gf[i], gf[i], ssf);

        float yv2 = g_y1[(size_t)bt * DINNER + j];
        float zv2 = g_zxbcdt[zb + j];
        gb[i] = yv2 * siluf(zv2);
        ssb = fmaf(gb[i], gb[i], ssb);
    }
    float sumf = blockReduceSum(ssf, sdata);
    float sumb = blockReduceSum(ssb, sdata);
    float rf = rsqrtf(sumf / DINNER + 1e-5f);
    float rb = rsqrtf(sumb / DINNER + 1e-5f);

    #pragma unroll
    for (int i = 0; i < 4; ++i) {
        int j = tid + i * 256;
        g_G[(size_t)bt * DINNER + j] = (gf[i] * rf + BETA * gb[i] * rb) * norm_w[j];
    }
}

// ---------------- LN1 --------------------------------------------------------
__global__ __launch_bounds__(256)
void ln1_kernel(const float* __restrict__ emb,
                const float* __restrict__ w, const float* __restrict__ bln)
{
    __shared__ float sdata[256];
    int bt = blockIdx.x;
    int tid = threadIdx.x;
    size_t base = (size_t)bt * DMODEL;

    float v[2], s = 0.0f, sq = 0.0f;
    #pragma unroll
    for (int i = 0; i < 2; ++i) {
        int j = tid + i * 256;
        v[i] = g_O[base + j] + emb[base + j];
        s += v[i];
        sq = fmaf(v[i], v[i], sq);
    }
    float sum = blockReduceSum(s, sdata);
    float sumsq = blockReduceSum(sq, sdata);
    float mu = sum / DMODEL;
    float var = sumsq / DMODEL - mu * mu;
    float rs = rsqrtf(var + 1e-12f);
    #pragma unroll
    for (int i = 0; i < 2; ++i) {
        int j = tid + i * 256;
        g_Xln[base + j] = (v[i] - mu) * rs * w[j] + bln[j];
    }
}

// ---------------- LN2 --------------------------------------------------------
__global__ __launch_bounds__(256)
void ln2_kernel(float* __restrict__ out,
                const float* __restrict__ w, const float* __restrict__ bln)
{
    __shared__ float sdata[256];
    int bt = blockIdx.x;
    int tid = threadIdx.x;
    size_t base = (size_t)bt * DMODEL;

    float v[2], s = 0.0f, sq = 0.0f;
    #pragma unroll
    for (int i = 0; i < 2; ++i) {
        int j = tid + i * 256;
        v[i] = g_H2[base + j] + g_Xln[base + j];
        s += v[i];
        sq = fmaf(v[i], v[i], sq);
    }
    float sum = blockReduceSum(s, sdata);
    float sumsq = blockReduceSum(sq, sdata);
    float mu = sum / DMODEL;
    float var = sumsq / DMODEL - mu * mu;
    float rs = rsqrtf(var + 1e-12f);
    #pragma unroll
    for (int i = 0; i < 2; ++i) {
        int j = tid + i * 256;
        out[base + j] = (v[i] - mu) * rs * w[j] + bln[j];
    }
}

// ---------------- launch -----------------------------------------------------
extern "C" void kernel_launch(void* const* d_in, const int* in_sizes, int n_in,
                              void* d_out, int out_size)
{
    const float* item_emb   = (const float*)d_in[0];
    const float* in_proj_w  = (const float*)d_in[3];
    const float* conv_w     = (const float*)d_in[4];
    const float* conv_b     = (const float*)d_in[5];
    const float* dt_bias    = (const float*)d_in[6];
    const float* A_log      = (const float*)d_in[7];
    const float* Dp         = (const float*)d_in[8];
    const float* norm_w     = (const float*)d_in[9];
    const float* out_proj_w = (const float*)d_in[10];
    const float* ln_w       = (const float*)d_in[11];
    const float* ln_b       = (const float*)d_in[12];
    const float* ffn_w1     = (const float*)d_in[13];
    const float* ffn_b1     = (const float*)d_in[14];
    const float* ffn_w2     = (const float*)d_in[15];
    const float* ffn_b2     = (const float*)d_in[16];
    const float* ffn_ln_w   = (const float*)d_in[17];
    const float* ffn_ln_b   = (const float*)d_in[18];
    float* out = (float*)d_out;

    float *p_zx, *p_G, *p_O, *p_Xln, *p_H1, *p_H2;
    cudaGetSymbolAddress((void**)&p_zx,  g_zxbcdt);
    cudaGetSymbolAddress((void**)&p_G,   g_G);
    cudaGetSymbolAddress((void**)&p_O,   g_O);
    cudaGetSymbolAddress((void**)&p_Xln, g_Xln);
    cudaGetSymbolAddress((void**)&p_H1,  g_H1);
    cudaGetSymbolAddress((void**)&p_H2,  g_H2);

    // 1) in_proj (8192 x 2192 x 512)
    {
        dim3 grid((DINPROJ + 127) / 128, NTOK / 128);
        h16gemm<0><<<grid, 256>>>(item_emb, in_proj_w, nullptr, p_zx, NTOK, DINPROJ, DMODEL);
    }

    // 2) conv + silu
    {
        int total = 2 * NTOK * (CONVDIM / 4);
        conv_silu_kernel<<<(total + 255) / 256, 256>>>(conv_w, conv_b);
    }

    // 3) dt softplus
    {
        int total = NTOK * NHEADS;
        dt_kernel<<<(total + 255) / 256, 256>>>(dt_bias);
    }

    // 4) SSD
    ssd_local_kernel<<<2048, 32>>>(A_log, Dp);
    ssd_combine_kernel<<<256, 64>>>();
    ssd_fixup_kernel<<<1536, 32>>>();

    // 5) gate + RMS + combine
    gate_rms_combine_kernel<<<NTOK, 256>>>(norm_w);

    // 6) out_proj (8192 x 512 x 1024)
    {
        dim3 grid(DMODEL / 128, NTOK / 128);
        h16gemm<0><<<grid, 256>>>(p_G, out_proj_w, nullptr, p_O, NTOK, DMODEL, DINNER);
    }

    // 7) LN1
    ln1_kernel<<<NTOK, 256>>>(item_emb, ln_w, ln_b);

    // 8) FFN1 (8192 x 2048 x 512)
    {
        dim3 grid(DFFN / 128, NTOK / 128);
        h16gemm<2><<<grid, 256>>>(p_Xln, ffn_w1, ffn_b1, p_H1, NTOK, DFFN, DMODEL);
    }

    // 9) FFN2 (8192 x 512 x 2048)
    {
        dim3 grid(DMODEL / 128, NTOK / 128);
        h16gemm<1><<<grid, 256>>>(p_H1, ffn_w2, ffn_b2, p_H2, NTOK, DMODEL, DFFN);
    }

    // 10) final LN
    ln2_kernel<<<NTOK, 256>>>(out, ffn_ln_w, ffn_ln_b);
}

// round 6
// speedup vs baseline: 1.2969x; 1.0048x over previous
#include <cuda_runtime.h>
#include <cuda_fp16.h>
#include <math.h>
#include <stdint.h>

#define BATCH   8
#define SEQLEN  1024
#define NTOK    (BATCH*SEQLEN)     // 8192
#define DMODEL  512
#define DSTATE  64
#define DINNER  1024
#define NHEADS  16
#define HEADDIM 64
#define DINPROJ 2192
#define DINPROJ_PAD 2304           // 18*128, zero-padded fp16 weights
#define CONVDIM 1152
#define DFFN    2048
#define BETA    0.5f
#define CHUNK   128
#define NCHUNK  8

// ---------------- scratch ----------------------------------------------------
__device__ float  g_zxbcdt[NTOK*DINPROJ];
__device__ float  g_xc0[NTOK*CONVDIM];
__device__ float  g_xc1[NTOK*CONVDIM];
__device__ float  g_dt [NTOK*NHEADS];
__device__ float  g_y0 [NTOK*DINNER];
__device__ float  g_y1 [NTOK*DINNER];
__device__ float  g_O  [NTOK*DMODEL];
__device__ float  g_Xln[NTOK*DMODEL];
__device__ float  g_H2 [NTOK*DMODEL];
__device__ float  g_cum[2*BATCH*NHEADS*SEQLEN];
__device__ float  g_L  [2*BATCH*NHEADS*NCHUNK*HEADDIM*DSTATE];
__device__ float  g_Hi [2*BATCH*NHEADS*NCHUNK*HEADDIM*DSTATE];
// fp16 operands
__device__ __half g_emb_h[NTOK*DMODEL];
__device__ __half g_Gh   [NTOK*DINNER];
__device__ __half g_Xh   [NTOK*DMODEL];
__device__ __half g_H1h  [NTOK*DFFN];
__device__ __half g_win_h [DINPROJ_PAD*DMODEL];
__device__ __half g_wout_h[DMODEL*DINNER];
__device__ __half g_w1_h  [DFFN*DMODEL];
__device__ __half g_w2_h  [DMODEL*DFFN];

// ---------------- helpers ----------------------------------------------------
__device__ __forceinline__ float siluf(float v) { return v / (1.0f + expf(-v)); }
__device__ __forceinline__ float geluf(float v) { return 0.5f * v * (1.0f + erff(v * 0.70710678118654752f)); }
__device__ __forceinline__ float softplusf(float x) { return fmaxf(x, 0.0f) + log1pf(expf(-fabsf(x))); }

__device__ __forceinline__ void cpasync16(uint32_t saddr, const void* gptr) {
    asm volatile("cp.async.cg.shared.global [%0], [%1], 16;\n" :: "r"(saddr), "l"(gptr));
}
__device__ __forceinline__ void cp_commit() { asm volatile("cp.async.commit_group;\n"); }
__device__ __forceinline__ void cp_wait0()  { asm volatile("cp.async.wait_group 0;\n"); }

__device__ __forceinline__ float blockReduceSum(float v, float* sdata) {
    int tid = threadIdx.x;
    sdata[tid] = v; __syncthreads();
    for (int s = blockDim.x >> 1; s > 0; s >>= 1) {
        if (tid < s) sdata[tid] += sdata[tid + s];
        __syncthreads();
    }
    float r = sdata[0]; __syncthreads();
    return r;
}

// ---------------- fp32 -> fp16 converters ------------------------------------
__global__ void cvt_kernel(const float* __restrict__ src, __half* __restrict__ dst, int n)
{
    int i = 4 * (blockIdx.x * blockDim.x + threadIdx.x);
    if (i >= n) return;
    float4 v = *(const float4*)&src[i];
    __half2* d = (__half2*)&dst[i];
    d[0] = __float22half2_rn(make_float2(v.x, v.y));
    d[1] = __float22half2_rn(make_float2(v.z, v.w));
}

// pad in_proj weights to 2304 rows (zeros beyond 2192)
__global__ void cvt_inproj_kernel(const float* __restrict__ src, __half* __restrict__ dst)
{
    int i = 4 * (blockIdx.x * blockDim.x + threadIdx.x);
    if (i >= DINPROJ_PAD * DMODEL) return;
    int row = i / DMODEL;
    __half2* d = (__half2*)&dst[i];
    if (row < DINPROJ) {
        float4 v = *(const float4*)&src[i];
        d[0] = __float22half2_rn(make_float2(v.x, v.y));
        d[1] = __float22half2_rn(make_float2(v.z, v.w));
    } else {
        d[0] = __half2(__float2half(0.f), __float2half(0.f));
        d[1] = __half2(__float2half(0.f), __float2half(0.f));
    }
}

// ---------------- FP16 GEMM (cp.async 2-stage): C = A[M,K] @ B[N,K]^T -------
// 128x128x32 tile, 256 threads (8 warps 2x4), warp tile 64x32 via m16n8k16.
// A, B already fp16. EPI: 0 none, 1 +bias, 2 gelu(+bias). OUTH: write half.
#define LDH 20   // uint32 words per smem row (40 halves: 32 data + 8 pad)

template<int EPI, int OUTH>
__global__ __launch_bounds__(256, 2)
void h16gemm(const __half* __restrict__ A, const __half* __restrict__ B,
             const float* __restrict__ bias, void* __restrict__ Cv,
             int M, int N, int K)
{
    __shared__ uint32_t As[2][128 * LDH];
    __shared__ uint32_t Bs[2][128 * LDH];

    const int tid = threadIdx.x;
    const int m0 = blockIdx.y * 128;
    const int n0 = blockIdx.x * 128;

    const int w    = tid >> 5;
    const int lane = tid & 31;
    const int wm   = (w >> 2) * 64;
    const int wn   = (w & 3) * 32;
    const int gr   = lane >> 2;
    const int gcw  = lane & 3;

    // cp.async mapping: 512 16B chunks per matrix per tile; thread does idx=tid, tid+256
    const int row0 = tid >> 2;               // 0..63
    const int c0   = tid & 3;                // chunk within row (16B = 8 halves)

    uint32_t asb = (uint32_t)__cvta_generic_to_shared(&As[0][0]);
    uint32_t bsb = (uint32_t)__cvta_generic_to_shared(&Bs[0][0]);
    const uint32_t bufstride = 128 * LDH * 4;

    float acc[4][4][4];
    #pragma unroll
    for (int i = 0; i < 4; ++i)
        #pragma unroll
        for (int j = 0; j < 4; ++j)
            #pragma unroll
            for (int r = 0; r < 4; ++r) acc[i][j][r] = 0.0f;

    const int KT = K / 32;

    // prologue: tile 0 -> buffer 0
    #pragma unroll
    for (int i = 0; i < 2; ++i) {
        int row = row0 + i * 64;
        uint32_t doff = (uint32_t)(row * 80 + c0 * 16);
        cpasync16(asb + doff, A + (size_t)(m0 + row) * K + c0 * 8);
        cpasync16(bsb + doff, B + (size_t)(n0 + row) * K + c0 * 8);
    }
    cp_commit();

    for (int kt = 0; kt < KT; ++kt) {
        const int cur = kt & 1;
        cp_wait0();
        __syncthreads();

        // issue next tile into the other buffer
        if (kt + 1 < KT) {
            const uint32_t nb = (uint32_t)((kt + 1) & 1) * bufstride;
            size_t koff = (size_t)(kt + 1) * 32 + c0 * 8;
            #pragma unroll
            for (int i = 0; i < 2; ++i) {
                int row = row0 + i * 64;
                uint32_t doff = nb + (uint32_t)(row * 80 + c0 * 16);
                cpasync16(asb + doff, A + (size_t)(m0 + row) * K + koff);
                cpasync16(bsb + doff, B + (size_t)(n0 + row) * K + koff);
            }
            cp_commit();
        }

        #pragma unroll
        for (int kk = 0; kk < 2; ++kk) {
            const int kw = kk * 8;
            uint32_t af[4][4];
            #pragma unroll
            for (int mi = 0; mi < 4; ++mi) {
                int r = wm + mi * 16 + gr;
                af[mi][0] = As[cur][r * LDH + kw + gcw];
                af[mi][1] = As[cur][(r + 8) * LDH + kw + gcw];
                af[mi][2] = As[cur][r * LDH + kw + gcw + 4];
                af[mi][3] = As[cur][(r + 8) * LDH + kw + gcw + 4];
            }
            uint32_t bf[4][2];
            #pragma unroll
            for (int ni = 0; ni < 4; ++ni) {
                int c = wn + ni * 8 + gr;
                bf[ni][0] = Bs[cur][c * LDH + kw + gcw];
                bf[ni][1] = Bs[cur][c * LDH + kw + gcw + 4];
            }
            #pragma unroll
            for (int mi = 0; mi < 4; ++mi)
                #pragma unroll
                for (int ni = 0; ni < 4; ++ni) {
                    asm volatile(
                        "mma.sync.aligned.m16n8k16.row.col.f32.f16.f16.f32 "
                        "{%0,%1,%2,%3}, {%4,%5,%6,%7}, {%8,%9}, {%0,%1,%2,%3};"
                        : "+f"(acc[mi][ni][0]), "+f"(acc[mi][ni][1]),
                          "+f"(acc[mi][ni][2]), "+f"(acc[mi][ni][3])
                        : "r"(af[mi][0]), "r"(af[mi][1]), "r"(af[mi][2]), "r"(af[mi][3]),
                          "r"(bf[ni][0]), "r"(bf[ni][1]));
                }
        }
        __syncthreads();   // all warps done with cur before it is refilled
    }

    float* Cf = (float*)Cv;
    __half* Ch = (__half*)Cv;
    #pragma unroll
    for (int mi = 0; mi < 4; ++mi) {
        int r = m0 + wm + mi * 16 + gr;
        #pragma unroll
        for (int ni = 0; ni < 4; ++ni) {
            int cb = n0 + wn + ni * 8 + 2 * gcw;
            #pragma unroll
            for (int half = 0; half < 2; ++half) {
                int rr = r + half * 8;
                float v0 = acc[mi][ni][half * 2 + 0];
                float v1 = acc[mi][ni][half * 2 + 1];
                if (cb < N) {
                    if (EPI >= 1) v0 += bias[cb];
                    if (EPI == 2) v0 = geluf(v0);
                    if (OUTH) Ch[(size_t)rr * N + cb] = __float2half_rn(v0);
                    else      Cf[(size_t)rr * N + cb] = v0;
                }
                if (cb + 1 < N) {
                    if (EPI >= 1) v1 += bias[cb + 1];
                    if (EPI == 2) v1 = geluf(v1);
                    if (OUTH) Ch[(size_t)rr * N + cb + 1] = __float2half_rn(v1);
                    else      Cf[(size_t)rr * N + cb + 1] = v1;
                }
            }
        }
    }
}

// ---------------- conv (causal depthwise, width 4) + silu, float4 -----------
__global__ void conv_silu_kernel(const float* __restrict__ conv_w,
                                 const float* __restrict__ conv_b)
{
    int e = blockIdx.x * blockDim.x + threadIdx.x;
    const int C4 = CONVDIM / 4;
    const int total = 2 * NTOK * C4;
    if (e >= total) return;
    int dir = e / (NTOK * C4);
    int rem = e - dir * (NTOK * C4);
    int bt = rem / C4;
    int c4 = rem % C4;
    int b = bt / SEQLEN;
    int t = bt % SEQLEN;
    int c = c4 * 4;

    float4 w0 = *(const float4*)&conv_w[(c + 0) * 4];
    float4 w1 = *(const float4*)&conv_w[(c + 1) * 4];
    float4 w2 = *(const float4*)&conv_w[(c + 2) * 4];
    float4 w3 = *(const float4*)&conv_w[(c + 3) * 4];
    float4 acc = *(const float4*)&conv_b[c];

    float wt0[4] = {w0.x, w0.y, w0.z, w0.w};
    float wt1[4] = {w1.x, w1.y, w1.z, w1.w};
    float wt2[4] = {w2.x, w2.y, w2.z, w2.w};
    float wt3[4] = {w3.x, w3.y, w3.z, w3.w};

    #pragma unroll
    for (int k = 0; k < 4; ++k) {
        int tp = t - 3 + k;
        if (tp >= 0) {
            int s = dir ? (SEQLEN - 1 - tp) : tp;
            float4 v = *(const float4*)&g_zxbcdt[(size_t)(b * SEQLEN + s) * DINPROJ + DINNER + c];
            acc.x = fmaf(wt0[k], v.x, acc.x);
            acc.y = fmaf(wt1[k], v.y, acc.y);
            acc.z = fmaf(wt2[k], v.z, acc.z);
            acc.w = fmaf(wt3[k], v.w, acc.w);
        }
    }
    acc.x = siluf(acc.x); acc.y = siluf(acc.y);
    acc.z = siluf(acc.z); acc.w = siluf(acc.w);
    float* out = dir ? g_xc1 : g_xc0;
    *(float4*)&out[(size_t)bt * CONVDIM + c] = acc;
}

// ---------------- dt = softplus(raw + bias) ---------------------------------
__global__ void dt_kernel(const float* __restrict__ dt_bias)
{
    int e = blockIdx.x * blockDim.x + threadIdx.x;
    if (e >= NTOK * NHEADS) return;
    int bt = e / NHEADS;
    int h  = e % NHEADS;
    float x = g_zxbcdt[(size_t)bt * DINPROJ + (DINNER + CONVDIM) + h] + dt_bias[h];
    g_dt[e] = softplusf(x);
}

// ---------------- SSD pass A: chunk-local scans (NCHUNK=8, unpipelined) -----
__global__ __launch_bounds__(32)
void ssd_local_kernel(const float* __restrict__ A_log,
                      const float* __restrict__ Dp)
{
    int blk   = blockIdx.x;                // 0..4095
    int half  = blk & 1;
    int chunk = (blk >> 1) & 7;
    int h     = (blk >> 4) & 15;
    int b     = (blk >> 8) & 7;
    int dir   = blk >> 11;
    int lane  = threadIdx.x;
    int p     = half * 32 + lane;

    const float* xc = dir ? g_xc1 : g_xc0;
    float* yout = dir ? g_y1 : g_y0;

    float A  = -expf(A_log[h]);
    float Dh = Dp[h];

    float st[64];
    #pragma unroll
    for (int n = 0; n < 64; ++n) st[n] = 0.0f;

    __shared__ float4 sBC[32];

    const size_t hb = (size_t)(dir * BATCH + b) * NHEADS + h;
    float cum = 1.0f;
    const int t0 = chunk * CHUNK;

    for (int tl = 0; tl < CHUNK; ++tl) {
        int t = t0 + tl;
        int tok = b * SEQLEN + t;
        size_t base = (size_t)tok * CONVDIM;

        __syncwarp();
        sBC[lane] = *(const float4*)&xc[base + DINNER + lane * 4];
        float xv = xc[base + h * HEADDIM + p];
        int s = dir ? (SEQLEN - 1 - t) : t;
        float dtv = g_dt[(size_t)(b * SEQLEN + s) * NHEADS + h];
        __syncwarp();

        float dA = expf(dtv * A);
        cum *= dA;
        if (half == 0 && lane == 0) g_cum[hb * SEQLEN + t] = cum;

        float coef = dtv * xv;
        float a0 = 0.f, a1 = 0.f, a2 = 0.f, a3 = 0.f;
        #pragma unroll
        for (int q = 0; q < 16; ++q) {
            float4 Bv = sBC[q];
            float4 Cv = sBC[16 + q];
            st[q*4+0] = fmaf(st[q*4+0], dA, coef * Bv.x); a0 = fmaf(st[q*4+0], Cv.x, a0);
            st[q*4+1] = fmaf(st[q*4+1], dA, coef * Bv.y); a1 = fmaf(st[q*4+1], Cv.y, a1);
            st[q*4+2] = fmaf(st[q*4+2], dA, coef * Bv.z); a2 = fmaf(st[q*4+2], Cv.z, a2);
            st[q*4+3] = fmaf(st[q*4+3], dA, coef * Bv.w); a3 = fmaf(st[q*4+3], Cv.w, a3);
        }
        yout[(size_t)tok * DINNER + h * HEADDIM + p] =
            (a0 + a1) + (a2 + a3) + xv * Dh;
    }

    size_t lb = ((hb * NCHUNK) + chunk) * (HEADDIM * DSTATE) + (size_t)p * DSTATE;
    #pragma unroll
    for (int q = 0; q < 16; ++q)
        *(float4*)&g_L[lb + q * 4] = make_float4(st[q*4], st[q*4+1], st[q*4+2], st[q*4+3]);
}

// ---------------- SSD pass B: sequential chunk-state combine -----------------
__global__ __launch_bounds__(64)
void ssd_combine_kernel()
{
    int blk = blockIdx.x;
    int h   = blk & 15;
    int b   = (blk >> 4) & 7;
    int dir = blk >> 7;
    int p   = threadIdx.x;

    const size_t hb = (size_t)(dir * BATCH + b) * NHEADS + h;

    float H[64];
    #pragma unroll
    for (int n = 0; n < 64; ++n) H[n] = 0.0f;

    for (int c = 0; c < NCHUNK; ++c) {
        size_t off = ((hb * NCHUNK) + c) * (HEADDIM * DSTATE) + (size_t)p * DSTATE;
        #pragma unroll
        for (int q = 0; q < 16; ++q)
            *(float4*)&g_Hi[off + q * 4] = make_float4(H[q*4], H[q*4+1], H[q*4+2], H[q*4+3]);
        if (c < NCHUNK - 1) {
            float P = g_cum[hb * SEQLEN + c * CHUNK + CHUNK - 1];
            #pragma unroll
            for (int q = 0; q < 16; ++q) {
                float4 L = *(const float4*)&g_L[off + q * 4];
                H[q*4+0] = fmaf(H[q*4+0], P, L.x);
                H[q*4+1] = fmaf(H[q*4+1], P, L.y);
                H[q*4+2] = fmaf(H[q*4+2], P, L.z);
                H[q*4+3] = fmaf(H[q*4+3], P, L.w);
            }
        }
    }
}

// ---------------- SSD pass C: fixup (chunks 1..7) ----------------------------
__global__ __launch_bounds__(32)
void ssd_fixup_kernel()
{
    int blk  = blockIdx.x;                 // 0..3583
    int half = blk & 1;
    int idx  = blk >> 1;
    int chunk = (idx % 7) + 1;
    idx /= 7;
    int h   = idx & 15;
    int b   = (idx >> 4) & 7;
    int dir = idx >> 7;
    int lane = threadIdx.x;
    int p    = half * 32 + lane;

    const float* xc = dir ? g_xc1 : g_xc0;
    float* yout = dir ? g_y1 : g_y0;
    const size_t hb = (size_t)(dir * BATCH + b) * NHEADS + h;

    float H[64];
    {
        size_t off = ((hb * NCHUNK) + chunk) * (HEADDIM * DSTATE) + (size_t)p * DSTATE;
        #pragma unroll
        for (int q = 0; q < 16; ++q) {
            float4 v = *(const float4*)&g_Hi[off + q * 4];
            H[q*4] = v.x; H[q*4+1] = v.y; H[q*4+2] = v.z; H[q*4+3] = v.w;
        }
    }

    __shared__ float4 sC[16];
    const int t0 = chunk * CHUNK;

    for (int tl = 0; tl < CHUNK; ++tl) {
        int t = t0 + tl;
        int tok = b * SEQLEN + t;
        size_t base = (size_t)tok * CONVDIM;

        __syncwarp();
        if (lane < 16)
            sC[lane] = *(const float4*)&xc[base + DINNER + DSTATE + lane * 4];
        __syncwarp();

        float cumv = g_cum[hb * SEQLEN + t];
        float a0 = 0.f, a1 = 0.f, a2 = 0.f, a3 = 0.f;
        #pragma unroll
        for (int q = 0; q < 16; ++q) {
            float4 Cv = sC[q];
            a0 = fmaf(H[q*4+0], Cv.x, a0);
            a1 = fmaf(H[q*4+1], Cv.y, a1);
            a2 = fmaf(H[q*4+2], Cv.z, a2);
            a3 = fmaf(H[q*4+3], Cv.w, a3);
        }
        size_t yi = (size_t)tok * DINNER + h * HEADDIM + p;
        yout[yi] = fmaf(cumv, (a0 + a1) + (a2 + a3), yout[yi]);
    }
}

// ---------------- gate + RMS + combine (writes fp16 G) -----------------------
__global__ __launch_bounds__(256)
void gate_rms_combine_kernel(const float* __restrict__ norm_w)
{
    __shared__ float sdata[256];
    int bt = blockIdx.x;
    int b = bt / SEQLEN;
    int t = bt % SEQLEN;
    int tid = threadIdx.x;

    float gf[4], gb[4];
    float ssf = 0.0f, ssb = 0.0f;
    size_t zf = (size_t)bt * DINPROJ;
    size_t zb = (size_t)(b * SEQLEN + (SEQLEN - 1 - t)) * DINPROJ;
    #pragma unroll
    for (int i = 0; i < 4; ++i) {
        int j = tid + i * 256;
        float yv = g_y0[(size_t)bt * DINNER + j];
        float zv = g_zxbcdt[zf + j];
        gf[i] = yv * siluf(zv);
        ssf = fmaf(gf[i], gf[i], ssf);

        float yv2 = g_y1[(size_t)bt * DINNER + j];
        float zv2 = g_zxbcdt[zb + j];
        gb[i] = yv2 * siluf(zv2);
        ssb = fmaf(gb[i], gb[i], ssb);
    }
    float sumf = blockReduceSum(ssf, sdata);
    float sumb = blockReduceSum(ssb, sdata);
    float rf = rsqrtf(sumf / DINNER + 1e-5f);
    float rb = rsqrtf(sumb / DINNER + 1e-5f);

    #pragma unroll
    for (int i = 0; i < 4; ++i) {
        int j = tid + i * 256;
        float v = (gf[i] * rf + BETA * gb[i] * rb) * norm_w[j];
        g_Gh[(size_t)bt * DINNER + j] = __float2half_rn(v);
    }
}

// ---------------- LN1: fp32 Xln + fp16 Xh ------------------------------------
__global__ __launch_bounds__(256)
void ln1_kernel(const float* __restrict__ emb,
                const float* __restrict__ w, const float* __restrict__ bln)
{
    __shared__ float sdata[256];
    int bt = blockIdx.x;
    int tid = threadIdx.x;
    size_t base = (size_t)bt * DMODEL;

    float v[2], s = 0.0f, sq = 0.0f;
    #pragma unroll
    for (int i = 0; i < 2; ++i) {
        int j = tid + i * 256;
        v[i] = g_O[base + j] + emb[base + j];
        s += v[i];
        sq = fmaf(v[i], v[i], sq);
    }
    float sum = blockReduceSum(s, sdata);
    float sumsq = blockReduceSum(sq, sdata);
    float mu = sum / DMODEL;
    float var = sumsq / DMODEL - mu * mu;
    float rs = rsqrtf(var + 1e-12f);
    #pragma unroll
    for (int i = 0; i < 2; ++i) {
        int j = tid + i * 256;
        float o = (v[i] - mu) * rs * w[j] + bln[j];
        g_Xln[base + j] = o;
        g_Xh [base + j] = __float2half_rn(o);
    }
}

// ---------------- LN2 --------------------------------------------------------
__global__ __launch_bounds__(256)
void ln2_kernel(float* __restrict__ out,
                const float* __restrict__ w, const float* __restrict__ bln)
{
    __shared__ float sdata[256];
    int bt = blockIdx.x;
    int tid = threadIdx.x;
    size_t base = (size_t)bt * DMODEL;

    float v[2], s = 0.0f, sq = 0.0f;
    #pragma unroll
    for (int i = 0; i < 2; ++i) {
        int j = tid + i * 256;
        v[i] = g_H2[base + j] + g_Xln[base + j];
        s += v[i];
        sq = fmaf(v[i], v[i], sq);
    }
    float sum = blockReduceSum(s, sdata);
    float sumsq = blockReduceSum(sq, sdata);
    float mu = sum / DMODEL;
    float var = sumsq / DMODEL - mu * mu;
    float rs = rsqrtf(var + 1e-12f);
    #pragma unroll
    for (int i = 0; i < 2; ++i) {
        int j = tid + i * 256;
        out[base + j] = (v[i] - mu) * rs * w[j] + bln[j];
    }
}

// ---------------- launch -----------------------------------------------------
extern "C" void kernel_launch(void* const* d_in, const int* in_sizes, int n_in,
                              void* d_out, int out_size)
{
    const float* item_emb   = (const float*)d_in[0];
    const float* in_proj_w  = (const float*)d_in[3];
    const float* conv_w     = (const float*)d_in[4];
    const float* conv_b     = (const float*)d_in[5];
    const float* dt_bias    = (const float*)d_in[6];
    const float* A_log      = (const float*)d_in[7];
    const float* Dp         = (const float*)d_in[8];
    const float* norm_w     = (const float*)d_in[9];
    const float* out_proj_w = (const float*)d_in[10];
    const float* ln_w       = (const float*)d_in[11];
    const float* ln_b       = (const float*)d_in[12];
    const float* ffn_w1     = (const float*)d_in[13];
    const float* ffn_b1     = (const float*)d_in[14];
    const float* ffn_w2     = (const float*)d_in[15];
    const float* ffn_b2     = (const float*)d_in[16];
    const float* ffn_ln_w   = (const float*)d_in[17];
    const float* ffn_ln_b   = (const float*)d_in[18];
    float* out = (float*)d_out;

    float *p_zx, *p_O, *p_H2;
    __half *p_embh, *p_Gh, *p_Xh, *p_H1h, *p_winh, *p_wouth, *p_w1h, *p_w2h;
    cudaGetSymbolAddress((void**)&p_zx,   g_zxbcdt);
    cudaGetSymbolAddress((void**)&p_O,    g_O);
    cudaGetSymbolAddress((void**)&p_H2,   g_H2);
    cudaGetSymbolAddress((void**)&p_embh, g_emb_h);
    cudaGetSymbolAddress((void**)&p_Gh,   g_Gh);
    cudaGetSymbolAddress((void**)&p_Xh,   g_Xh);
    cudaGetSymbolAddress((void**)&p_H1h,  g_H1h);
    cudaGetSymbolAddress((void**)&p_winh, g_win_h);
    cudaGetSymbolAddress((void**)&p_wouth,g_wout_h);
    cudaGetSymbolAddress((void**)&p_w1h,  g_w1_h);
    cudaGetSymbolAddress((void**)&p_w2h,  g_w2_h);

    // 0) fp16 conversions
    cvt_kernel<<<(NTOK*DMODEL/4 + 255)/256, 256>>>(item_emb, p_embh, NTOK*DMODEL);
    cvt_inproj_kernel<<<(DINPROJ_PAD*DMODEL/4 + 255)/256, 256>>>(in_proj_w, p_winh);
    cvt_kernel<<<(DMODEL*DINNER/4 + 255)/256, 256>>>(out_proj_w, p_wouth, DMODEL*DINNER);
    cvt_kernel<<<(DFFN*DMODEL/4 + 255)/256, 256>>>(ffn_w1, p_w1h, DFFN*DMODEL);
    cvt_kernel<<<(DMODEL*DFFN/4 + 255)/256, 256>>>(ffn_w2, p_w2h, DMODEL*DFFN);

    // 1) in_proj (8192 x 2192 x 512), N padded to 2304 in weights
    {
        dim3 grid(DINPROJ_PAD / 128, NTOK / 128);
        h16gemm<0,0><<<grid, 256>>>(p_embh, p_winh, nullptr, p_zx, NTOK, DINPROJ, DMODEL);
    }

    // 2) conv + silu
    {
        int total = 2 * NTOK * (CONVDIM / 4);
        conv_silu_kernel<<<(total + 255) / 256, 256>>>(conv_w, conv_b);
    }

    // 3) dt softplus
    {
        int total = NTOK * NHEADS;
        dt_kernel<<<(total + 255) / 256, 256>>>(dt_bias);
    }

    // 4) SSD
    ssd_local_kernel<<<4096, 32>>>(A_log, Dp);
    ssd_combine_kernel<<<256, 64>>>();
    ssd_fixup_kernel<<<3584, 32>>>();

    // 5) gate + RMS + combine -> fp16 G
    gate_rms_combine_kernel<<<NTOK, 256>>>(norm_w);

    // 6) out_proj (8192 x 512 x 1024)
    {
        dim3 grid(DMODEL / 128, NTOK / 128);
        h16gemm<0,0><<<grid, 256>>>(p_Gh, p_wouth, nullptr, p_O, NTOK, DMODEL, DINNER);
    }

    // 7) LN1 -> fp32 + fp16
    ln1_kernel<<<NTOK, 256>>>(item_emb, ln_w, ln_b);

    // 8) FFN1 (8192 x 2048 x 512), gelu, fp16 out
    {
        dim3 grid(DFFN / 128, NTOK / 128);
        h16gemm<2,1><<<grid, 256>>>(p_Xh, p_w1h, ffn_b1, p_H1h, NTOK, DFFN, DMODEL);
    }

    // 9) FFN2 (8192 x 512 x 2048)
    {
        dim3 grid(DMODEL / 128, NTOK / 128);
        h16gemm<1,0><<<grid, 256>>>(p_H1h, p_w2h, ffn_b2, p_H2, NTOK, DMODEL, DFFN);
    }

    // 10) final LN
    ln2_kernel<<<NTOK, 256>>>(out, ffn_ln_w, ffn_ln_b);
}

// round 7
// speedup vs baseline: 1.5437x; 1.1903x over previous
#include <cuda_runtime.h>
#include <cuda_fp16.h>
#include <math.h>
#include <stdint.h>

#define BATCH   8
#define SEQLEN  1024
#define NTOK    (BATCH*SEQLEN)     // 8192
#define DMODEL  512
#define DSTATE  64
#define DINNER  1024
#define NHEADS  16
#define HEADDIM 64
#define DINPROJ 2192
#define DINPROJ_PAD 2304
#define CONVDIM 1152
#define DFFN    2048
#define BETA    0.5f
#define CHUNK   128
#define NCHUNK  8

// ---------------- scratch ----------------------------------------------------
__device__ float  g_zxbcdt[NTOK*DINPROJ];
__device__ float  g_xc0[NTOK*CONVDIM];
__device__ float  g_xc1[NTOK*CONVDIM];
__device__ float  g_dt [NTOK*NHEADS];
__device__ float  g_y0 [NTOK*DINNER];
__device__ float  g_y1 [NTOK*DINNER];
__device__ float  g_O  [NTOK*DMODEL];
__device__ float  g_Xln[NTOK*DMODEL];
__device__ float  g_H2 [NTOK*DMODEL];
__device__ float  g_cum[2*BATCH*NHEADS*SEQLEN];
__device__ float  g_L  [2*BATCH*NHEADS*NCHUNK*HEADDIM*DSTATE];
__device__ float  g_Hi [2*BATCH*NHEADS*NCHUNK*HEADDIM*DSTATE];
// fp16 operands
__device__ __half g_emb_h[NTOK*DMODEL];
__device__ __half g_Gh   [NTOK*DINNER];
__device__ __half g_Xh   [NTOK*DMODEL];
__device__ __half g_H1h  [NTOK*DFFN];
__device__ __half g_win_h [DINPROJ_PAD*DMODEL];
__device__ __half g_wout_h[DMODEL*DINNER];
__device__ __half g_w1_h  [DFFN*DMODEL];
__device__ __half g_w2_h  [DMODEL*DFFN];

// ---------------- helpers ----------------------------------------------------
__device__ __forceinline__ float siluf(float v) { return v / (1.0f + expf(-v)); }
__device__ __forceinline__ float geluf(float v) { return 0.5f * v * (1.0f + erff(v * 0.70710678118654752f)); }
__device__ __forceinline__ float softplusf(float x) { return fmaxf(x, 0.0f) + log1pf(expf(-fabsf(x))); }

__device__ __forceinline__ void cpasync16(uint32_t saddr, const void* gptr) {
    asm volatile("cp.async.cg.shared.global [%0], [%1], 16;\n" :: "r"(saddr), "l"(gptr));
}
__device__ __forceinline__ void cp_commit() { asm volatile("cp.async.commit_group;\n"); }
__device__ __forceinline__ void cp_wait0()  { asm volatile("cp.async.wait_group 0;\n"); }
__device__ __forceinline__ void cp_wait1()  { asm volatile("cp.async.wait_group 1;\n"); }

__device__ __forceinline__ float blockReduceSum(float v, float* sdata) {
    int tid = threadIdx.x;
    sdata[tid] = v; __syncthreads();
    for (int s = blockDim.x >> 1; s > 0; s >>= 1) {
        if (tid < s) sdata[tid] += sdata[tid + s];
        __syncthreads();
    }
    float r = sdata[0]; __syncthreads();
    return r;
}
__device__ __forceinline__ uint32_t pack2h(float x, float y) {
    __half2 h = __float22half2_rn(make_float2(x, y));
    return *(uint32_t*)&h;
}

// ---------------- fp32 -> fp16 converters ------------------------------------
__global__ void cvt_kernel(const float* __restrict__ src, __half* __restrict__ dst, int n)
{
    int i = 4 * (blockIdx.x * blockDim.x + threadIdx.x);
    if (i >= n) return;
    float4 v = *(const float4*)&src[i];
    __half2* d = (__half2*)&dst[i];
    d[0] = __float22half2_rn(make_float2(v.x, v.y));
    d[1] = __float22half2_rn(make_float2(v.z, v.w));
}

__global__ void cvt_inproj_kernel(const float* __restrict__ src, __half* __restrict__ dst)
{
    int i = 4 * (blockIdx.x * blockDim.x + threadIdx.x);
    if (i >= DINPROJ_PAD * DMODEL) return;
    int row = i / DMODEL;
    __half2* d = (__half2*)&dst[i];
    if (row < DINPROJ) {
        float4 v = *(const float4*)&src[i];
        d[0] = __float22half2_rn(make_float2(v.x, v.y));
        d[1] = __float22half2_rn(make_float2(v.z, v.w));
    } else {
        d[0] = __half2(__float2half(0.f), __float2half(0.f));
        d[1] = __half2(__float2half(0.f), __float2half(0.f));
    }
}

// ---------------- FP16 GEMM (cp.async 3-stage): C = A[M,K] @ B[N,K]^T -------
// 128x128x32 tile, 256 threads (8 warps 2x4), warp tile 64x32 via m16n8k16.
// Dynamic smem: 3 stages x (A 10240B + B 10240B) = 61440B.
#define LDH 20                 // uint32 words per smem row (40 halves)
#define TILE_W (128 * LDH)     // words per matrix per stage (2560)
#define GEMM_SMEM (6 * TILE_W * 4)

template<int EPI, int OUTH>
__global__ __launch_bounds__(256, 2)
void h16gemm(const __half* __restrict__ A, const __half* __restrict__ B,
             const float* __restrict__ bias, void* __restrict__ Cv,
             int M, int N, int K)
{
    extern __shared__ uint32_t smemu[];
    uint32_t* AsB = smemu;                 // 3 stages
    uint32_t* BsB = smemu + 3 * TILE_W;

    const int tid = threadIdx.x;
    const int m0 = blockIdx.y * 128;
    const int n0 = blockIdx.x * 128;

    const int w    = tid >> 5;
    const int lane = tid & 31;
    const int wm   = (w >> 2) * 64;
    const int wn   = (w & 3) * 32;
    const int gr   = lane >> 2;
    const int gcw  = lane & 3;

    const int row0 = tid >> 2;
    const int c0   = tid & 3;

    uint32_t asb = (uint32_t)__cvta_generic_to_shared(AsB);
    uint32_t bsb = (uint32_t)__cvta_generic_to_shared(BsB);
    const uint32_t stg = TILE_W * 4;

    float acc[4][4][4];
    #pragma unroll
    for (int i = 0; i < 4; ++i)
        #pragma unroll
        for (int j = 0; j < 4; ++j)
            #pragma unroll
            for (int r = 0; r < 4; ++r) acc[i][j][r] = 0.0f;

    const int KT = K / 32;

    // prologue: issue tiles 0 and 1
    #pragma unroll
    for (int t = 0; t < 2; ++t) {
        if (t < KT) {
            size_t koff = (size_t)t * 32 + c0 * 8;
            #pragma unroll
            for (int i = 0; i < 2; ++i) {
                int row = row0 + i * 64;
                uint32_t doff = (uint32_t)t * stg + (uint32_t)(row * 80 + c0 * 16);
                cpasync16(asb + doff, A + (size_t)(m0 + row) * K + koff);
                cpasync16(bsb + doff, B + (size_t)(n0 + row) * K + koff);
            }
            cp_commit();
        }
    }

    int cur = 0;
    for (int kt = 0; kt < KT; ++kt) {
        if (kt + 1 < KT) cp_wait1(); else cp_wait0();
        __syncthreads();

        // issue tile kt+2 into stage (kt+2)%3
        if (kt + 2 < KT) {
            int nb = cur + 2; if (nb >= 3) nb -= 3;
            size_t koff = (size_t)(kt + 2) * 32 + c0 * 8;
            #pragma unroll
            for (int i = 0; i < 2; ++i) {
                int row = row0 + i * 64;
                uint32_t doff = (uint32_t)nb * stg + (uint32_t)(row * 80 + c0 * 16);
                cpasync16(asb + doff, A + (size_t)(m0 + row) * K + koff);
                cpasync16(bsb + doff, B + (size_t)(n0 + row) * K + koff);
            }
            cp_commit();
        }

        const uint32_t* As = AsB + cur * TILE_W;
        const uint32_t* Bs = BsB + cur * TILE_W;
        #pragma unroll
        for (int kk = 0; kk < 2; ++kk) {
            const int kw = kk * 8;
            uint32_t af[4][4];
            #pragma unroll
            for (int mi = 0; mi < 4; ++mi) {
                int r = wm + mi * 16 + gr;
                af[mi][0] = As[r * LDH + kw + gcw];
                af[mi][1] = As[(r + 8) * LDH + kw + gcw];
                af[mi][2] = As[r * LDH + kw + gcw + 4];
                af[mi][3] = As[(r + 8) * LDH + kw + gcw + 4];
            }
            uint32_t bf[4][2];
            #pragma unroll
            for (int ni = 0; ni < 4; ++ni) {
                int c = wn + ni * 8 + gr;
                bf[ni][0] = Bs[c * LDH + kw + gcw];
                bf[ni][1] = Bs[c * LDH + kw + gcw + 4];
            }
            #pragma unroll
            for (int mi = 0; mi < 4; ++mi)
                #pragma unroll
                for (int ni = 0; ni < 4; ++ni) {
                    asm volatile(
                        "mma.sync.aligned.m16n8k16.row.col.f32.f16.f16.f32 "
                        "{%0,%1,%2,%3}, {%4,%5,%6,%7}, {%8,%9}, {%0,%1,%2,%3};"
                        : "+f"(acc[mi][ni][0]), "+f"(acc[mi][ni][1]),
                          "+f"(acc[mi][ni][2]), "+f"(acc[mi][ni][3])
                        : "r"(af[mi][0]), "r"(af[mi][1]), "r"(af[mi][2]), "r"(af[mi][3]),
                          "r"(bf[ni][0]), "r"(bf[ni][1]));
                }
        }
        __syncthreads();
        if (++cur == 3) cur = 0;
    }

    float* Cf = (float*)Cv;
    __half* Ch = (__half*)Cv;
    #pragma unroll
    for (int mi = 0; mi < 4; ++mi) {
        int r = m0 + wm + mi * 16 + gr;
        #pragma unroll
        for (int ni = 0; ni < 4; ++ni) {
            int cb = n0 + wn + ni * 8 + 2 * gcw;
            #pragma unroll
            for (int half = 0; half < 2; ++half) {
                int rr = r + half * 8;
                float v0 = acc[mi][ni][half * 2 + 0];
                float v1 = acc[mi][ni][half * 2 + 1];
                if (cb < N) {
                    if (EPI >= 1) v0 += bias[cb];
                    if (EPI == 2) v0 = geluf(v0);
                    if (OUTH) Ch[(size_t)rr * N + cb] = __float2half_rn(v0);
                    else      Cf[(size_t)rr * N + cb] = v0;
                }
                if (cb + 1 < N) {
                    if (EPI >= 1) v1 += bias[cb + 1];
                    if (EPI == 2) v1 = geluf(v1);
                    if (OUTH) Ch[(size_t)rr * N + cb + 1] = __float2half_rn(v1);
                    else      Cf[(size_t)rr * N + cb + 1] = v1;
                }
            }
        }
    }
}

// ---------------- conv + silu (float4) ---------------------------------------
__global__ void conv_silu_kernel(const float* __restrict__ conv_w,
                                 const float* __restrict__ conv_b)
{
    int e = blockIdx.x * blockDim.x + threadIdx.x;
    const int C4 = CONVDIM / 4;
    const int total = 2 * NTOK * C4;
    if (e >= total) return;
    int dir = e / (NTOK * C4);
    int rem = e - dir * (NTOK * C4);
    int bt = rem / C4;
    int c4 = rem % C4;
    int b = bt / SEQLEN;
    int t = bt % SEQLEN;
    int c = c4 * 4;

    float4 w0 = *(const float4*)&conv_w[(c + 0) * 4];
    float4 w1 = *(const float4*)&conv_w[(c + 1) * 4];
    float4 w2 = *(const float4*)&conv_w[(c + 2) * 4];
    float4 w3 = *(const float4*)&conv_w[(c + 3) * 4];
    float4 acc = *(const float4*)&conv_b[c];

    float wt0[4] = {w0.x, w0.y, w0.z, w0.w};
    float wt1[4] = {w1.x, w1.y, w1.z, w1.w};
    float wt2[4] = {w2.x, w2.y, w2.z, w2.w};
    float wt3[4] = {w3.x, w3.y, w3.z, w3.w};

    #pragma unroll
    for (int k = 0; k < 4; ++k) {
        int tp = t - 3 + k;
        if (tp >= 0) {
            int s = dir ? (SEQLEN - 1 - tp) : tp;
            float4 v = *(const float4*)&g_zxbcdt[(size_t)(b * SEQLEN + s) * DINPROJ + DINNER + c];
            acc.x = fmaf(wt0[k], v.x, acc.x);
            acc.y = fmaf(wt1[k], v.y, acc.y);
            acc.z = fmaf(wt2[k], v.z, acc.z);
            acc.w = fmaf(wt3[k], v.w, acc.w);
        }
    }
    acc.x = siluf(acc.x); acc.y = siluf(acc.y);
    acc.z = siluf(acc.z); acc.w = siluf(acc.w);
    float* out = dir ? g_xc1 : g_xc0;
    *(float4*)&out[(size_t)bt * CONVDIM + c] = acc;
}

// ---------------- dt = softplus(raw + bias) ---------------------------------
__global__ void dt_kernel(const float* __restrict__ dt_bias)
{
    int e = blockIdx.x * blockDim.x + threadIdx.x;
    if (e >= NTOK * NHEADS) return;
    int bt = e / NHEADS;
    int h  = e % NHEADS;
    float x = g_zxbcdt[(size_t)bt * DINPROJ + (DINNER + CONVDIM) + h] + dt_bias[h];
    g_dt[e] = softplusf(x);
}

// ---------------- SSD pass A: chunk-local scans ------------------------------
__global__ __launch_bounds__(32)
void ssd_local_kernel(const float* __restrict__ A_log,
                      const float* __restrict__ Dp)
{
    int blk   = blockIdx.x;
    int half  = blk & 1;
    int chunk = (blk >> 1) & 7;
    int h     = (blk >> 4) & 15;
    int b     = (blk >> 8) & 7;
    int dir   = blk >> 11;
    int lane  = threadIdx.x;
    int p     = half * 32 + lane;

    const float* xc = dir ? g_xc1 : g_xc0;
    float* yout = dir ? g_y1 : g_y0;

    float A  = -expf(A_log[h]);
    float Dh = Dp[h];

    float st[64];
    #pragma unroll
    for (int n = 0; n < 64; ++n) st[n] = 0.0f;

    __shared__ float4 sBC[32];

    const size_t hb = (size_t)(dir * BATCH + b) * NHEADS + h;
    float cum = 1.0f;
    const int t0 = chunk * CHUNK;

    for (int tl = 0; tl < CHUNK; ++tl) {
        int t = t0 + tl;
        int tok = b * SEQLEN + t;
        size_t base = (size_t)tok * CONVDIM;

        __syncwarp();
        sBC[lane] = *(const float4*)&xc[base + DINNER + lane * 4];
        float xv = xc[base + h * HEADDIM + p];
        int s = dir ? (SEQLEN - 1 - t) : t;
        float dtv = g_dt[(size_t)(b * SEQLEN + s) * NHEADS + h];
        __syncwarp();

        float dA = expf(dtv * A);
        cum *= dA;
        if (half == 0 && lane == 0) g_cum[hb * SEQLEN + t] = cum;

        float coef = dtv * xv;
        float a0 = 0.f, a1 = 0.f, a2 = 0.f, a3 = 0.f;
        #pragma unroll
        for (int q = 0; q < 16; ++q) {
            float4 Bv = sBC[q];
            float4 Cv = sBC[16 + q];
            st[q*4+0] = fmaf(st[q*4+0], dA, coef * Bv.x); a0 = fmaf(st[q*4+0], Cv.x, a0);
            st[q*4+1] = fmaf(st[q*4+1], dA, coef * Bv.y); a1 = fmaf(st[q*4+1], Cv.y, a1);
            st[q*4+2] = fmaf(st[q*4+2], dA, coef * Bv.z); a2 = fmaf(st[q*4+2], Cv.z, a2);
            st[q*4+3] = fmaf(st[q*4+3], dA, coef * Bv.w); a3 = fmaf(st[q*4+3], Cv.w, a3);
        }
        yout[(size_t)tok * DINNER + h * HEADDIM + p] =
            (a0 + a1) + (a2 + a3) + xv * Dh;
    }

    size_t lb = ((hb * NCHUNK) + chunk) * (HEADDIM * DSTATE) + (size_t)p * DSTATE;
    #pragma unroll
    for (int q = 0; q < 16; ++q)
        *(float4*)&g_L[lb + q * 4] = make_float4(st[q*4], st[q*4+1], st[q*4+2], st[q*4+3]);
}

// ---------------- SSD pass B: sequential chunk-state combine -----------------
__global__ __launch_bounds__(64)
void ssd_combine_kernel()
{
    int blk = blockIdx.x;
    int h   = blk & 15;
    int b   = (blk >> 4) & 7;
    int dir = blk >> 7;
    int p   = threadIdx.x;

    const size_t hb = (size_t)(dir * BATCH + b) * NHEADS + h;

    float H[64];
    #pragma unroll
    for (int n = 0; n < 64; ++n) H[n] = 0.0f;

    for (int c = 0; c < NCHUNK; ++c) {
        size_t off = ((hb * NCHUNK) + c) * (HEADDIM * DSTATE) + (size_t)p * DSTATE;
        #pragma unroll
        for (int q = 0; q < 16; ++q)
            *(float4*)&g_Hi[off + q * 4] = make_float4(H[q*4], H[q*4+1], H[q*4+2], H[q*4+3]);
        if (c < NCHUNK - 1) {
            float P = g_cum[hb * SEQLEN + c * CHUNK + CHUNK - 1];
            #pragma unroll
            for (int q = 0; q < 16; ++q) {
                float4 L = *(const float4*)&g_L[off + q * 4];
                H[q*4+0] = fmaf(H[q*4+0], P, L.x);
                H[q*4+1] = fmaf(H[q*4+1], P, L.y);
                H[q*4+2] = fmaf(H[q*4+2], P, L.z);
                H[q*4+3] = fmaf(H[q*4+3], P, L.w);
            }
        }
    }
}

// ---------------- SSD pass C: fixup as tensor-core GEMM ----------------------
// Per (dir,b,h,chunk>=1): Y[t,p] += cum[t] * (C[t,:] @ H[:,p])
// M=CHUNK=128 tokens, N=64 (p), K=64 (n). 128 threads = 4 warps, warp = 32 rows.
#define LDF 36   // uint32 words per smem row (72 halves: 64 data + 8 pad)

__global__ __launch_bounds__(128)
void ssd_fixup_mma_kernel()
{
    __shared__ uint32_t Ash[128 * LDF];   // C tokens x n   (18 KB)
    __shared__ uint32_t Bsh[64 * LDF];    // H^T: p x n     (9 KB)

    int idx  = blockIdx.x;                // 0..1791
    int chunk = (idx % (NCHUNK - 1)) + 1;
    idx /= (NCHUNK - 1);
    int h   = idx & 15;
    int b   = (idx >> 4) & 7;
    int dir = idx >> 7;

    const float* xc = dir ? g_xc1 : g_xc0;
    float* yout = dir ? g_y1 : g_y0;
    const size_t hb = (size_t)(dir * BATCH + b) * NHEADS + h;
    const int t0 = chunk * CHUNK;
    const int tid = threadIdx.x;
    const int w    = tid >> 5;
    const int lane = tid & 31;
    const int gr   = lane >> 2;
    const int gcw  = lane & 3;

    // stage A: C rows (128 tokens x 64 floats -> fp16)
    #pragma unroll
    for (int i = 0; i < 16; ++i) {
        int id = tid + i * 128;           // 0..2047
        int row = id >> 4;
        int f4  = id & 15;
        float4 v = *(const float4*)&xc[(size_t)(b * SEQLEN + t0 + row) * CONVDIM
                                       + DINNER + DSTATE + f4 * 4];
        Ash[row * LDF + f4 * 2 + 0] = pack2h(v.x, v.y);
        Ash[row * LDF + f4 * 2 + 1] = pack2h(v.z, v.w);
    }
    // stage B: H (g_Hi is [p][n] row-major = the [N,K] operand)
    {
        size_t hbase = ((hb * NCHUNK) + chunk) * (HEADDIM * DSTATE);
        #pragma unroll
        for (int i = 0; i < 8; ++i) {
            int id = tid + i * 128;       // 0..1023
            int row = id >> 4;
            int f4  = id & 15;
            float4 v = *(const float4*)&g_Hi[hbase + (size_t)row * DSTATE + f4 * 4];
            Bsh[row * LDF + f4 * 2 + 0] = pack2h(v.x, v.y);
            Bsh[row * LDF + f4 * 2 + 1] = pack2h(v.z, v.w);
        }
    }
    __syncthreads();

    float acc[2][8][4];
    #pragma unroll
    for (int i = 0; i < 2; ++i)
        #pragma unroll
        for (int j = 0; j < 8; ++j)
            #pragma unroll
            for (int r = 0; r < 4; ++r) acc[i][j][r] = 0.0f;

    #pragma unroll
    for (int kk = 0; kk < 4; ++kk) {
        const int kw = kk * 8;
        uint32_t af[2][4];
        #pragma unroll
        for (int mi = 0; mi < 2; ++mi) {
            int r = w * 32 + mi * 16 + gr;
            af[mi][0] = Ash[r * LDF + kw + gcw];
            af[mi][1] = Ash[(r + 8) * LDF + kw + gcw];
            af[mi][2] = Ash[r * LDF + kw + gcw + 4];
            af[mi][3] = Ash[(r + 8) * LDF + kw + gcw + 4];
        }
        uint32_t bf[8][2];
        #pragma unroll
        for (int ni = 0; ni < 8; ++ni) {
            int c = ni * 8 + gr;
            bf[ni][0] = Bsh[c * LDF + kw + gcw];
            bf[ni][1] = Bsh[c * LDF + kw + gcw + 4];
        }
        #pragma unroll
        for (int mi = 0; mi < 2; ++mi)
            #pragma unroll
            for (int ni = 0; ni < 8; ++ni) {
                asm volatile(
                    "mma.sync.aligned.m16n8k16.row.col.f32.f16.f16.f32 "
                    "{%0,%1,%2,%3}, {%4,%5,%6,%7}, {%8,%9}, {%0,%1,%2,%3};"
                    : "+f"(acc[mi][ni][0]), "+f"(acc[mi][ni][1]),
                      "+f"(acc[mi][ni][2]), "+f"(acc[mi][ni][3])
                    : "r"(af[mi][0]), "r"(af[mi][1]), "r"(af[mi][2]), "r"(af[mi][3]),
                      "r"(bf[ni][0]), "r"(bf[ni][1]));
            }
    }

    // epilogue: y += cum[t] * acc
    #pragma unroll
    for (int mi = 0; mi < 2; ++mi) {
        int rbase = w * 32 + mi * 16 + gr;
        #pragma unroll
        for (int half = 0; half < 2; ++half) {
            int rr = rbase + half * 8;
            int tok = b * SEQLEN + t0 + rr;
            float cumv = g_cum[hb * SEQLEN + t0 + rr];
            size_t ybase = (size_t)tok * DINNER + h * HEADDIM;
            #pragma unroll
            for (int ni = 0; ni < 8; ++ni) {
                int cb = ni * 8 + 2 * gcw;
                float v0 = acc[mi][ni][half * 2 + 0];
                float v1 = acc[mi][ni][half * 2 + 1];
                yout[ybase + cb]     += cumv * v0;
                yout[ybase + cb + 1] += cumv * v1;
            }
        }
    }
}

// ---------------- gate + RMS + combine (writes fp16 G) -----------------------
__global__ __launch_bounds__(256)
void gate_rms_combine_kernel(const float* __restrict__ norm_w)
{
    __shared__ float sdata[256];
    int bt = blockIdx.x;
    int b = bt / SEQLEN;
    int t = bt % SEQLEN;
    int tid = threadIdx.x;

    float gf[4], gb[4];
    float ssf = 0.0f, ssb = 0.0f;
    size_t zf = (size_t)bt * DINPROJ;
    size_t zb = (size_t)(b * SEQLEN + (SEQLEN - 1 - t)) * DINPROJ;
    #pragma unroll
    for (int i = 0; i < 4; ++i) {
        int j = tid + i * 256;
        float yv = g_y0[(size_t)bt * DINNER + j];
        float zv = g_zxbcdt[zf + j];
        gf[i] = yv * siluf(zv);
        ssf = fmaf(gf[i], gf[i], ssf);

        float yv2 = g_y1[(size_t)bt * DINNER + j];
        float zv2 = g_zxbcdt[zb + j];
        gb[i] = yv2 * siluf(zv2);
        ssb = fmaf(gb[i], gb[i], ssb);
    }
    float sumf = blockReduceSum(ssf, sdata);
    float sumb = blockReduceSum(ssb, sdata);
    float rf = rsqrtf(sumf / DINNER + 1e-5f);
    float rb = rsqrtf(sumb / DINNER + 1e-5f);

    #pragma unroll
    for (int i = 0; i < 4; ++i) {
        int j = tid + i * 256;
        float v = (gf[i] * rf + BETA * gb[i] * rb) * norm_w[j];
        g_Gh[(size_t)bt * DINNER + j] = __float2half_rn(v);
    }
}

// ---------------- LN1 ---------------------------------------------------------
__global__ __launch_bounds__(256)
void ln1_kernel(const float* __restrict__ emb,
                const float* __restrict__ w, const float* __restrict__ bln)
{
    __shared__ float sdata[256];
    int bt = blockIdx.x;
    int tid = threadIdx.x;
    size_t base = (size_t)bt * DMODEL;

    float v[2], s = 0.0f, sq = 0.0f;
    #pragma unroll
    for (int i = 0; i < 2; ++i) {
        int j = tid + i * 256;
        v[i] = g_O[base + j] + emb[base + j];
        s += v[i];
        sq = fmaf(v[i], v[i], sq);
    }
    float sum = blockReduceSum(s, sdata);
    float sumsq = blockReduceSum(sq, sdata);
    float mu = sum / DMODEL;
    float var = sumsq / DMODEL - mu * mu;
    float rs = rsqrtf(var + 1e-12f);
    #pragma unroll
    for (int i = 0; i < 2; ++i) {
        int j = tid + i * 256;
        float o = (v[i] - mu) * rs * w[j] + bln[j];
        g_Xln[base + j] = o;
        g_Xh [base + j] = __float2half_rn(o);
    }
}

// ---------------- LN2 ---------------------------------------------------------
__global__ __launch_bounds__(256)
void ln2_kernel(float* __restrict__ out,
                const float* __restrict__ w, const float* __restrict__ bln)
{
    __shared__ float sdata[256];
    int bt = blockIdx.x;
    int tid = threadIdx.x;
    size_t base = (size_t)bt * DMODEL;

    float v[2], s = 0.0f, sq = 0.0f;
    #pragma unroll
    for (int i = 0; i < 2; ++i) {
        int j = tid + i * 256;
        v[i] = g_H2[base + j] + g_Xln[base + j];
        s += v[i];
        sq = fmaf(v[i], v[i], sq);
    }
    float sum = blockReduceSum(s, sdata);
    float sumsq = blockReduceSum(sq, sdata);
    float mu = sum / DMODEL;
    float var = sumsq / DMODEL - mu * mu;
    float rs = rsqrtf(var + 1e-12f);
    #pragma unroll
    for (int i = 0; i < 2; ++i) {
        int j = tid + i * 256;
        out[base + j] = (v[i] - mu) * rs * w[j] + bln[j];
    }
}

// ---------------- launch -----------------------------------------------------
extern "C" void kernel_launch(void* const* d_in, const int* in_sizes, int n_in,
                              void* d_out, int out_size)
{
    const float* item_emb   = (const float*)d_in[0];
    const float* in_proj_w  = (const float*)d_in[3];
    const float* conv_w     = (const float*)d_in[4];
    const float* conv_b     = (const float*)d_in[5];
    const float* dt_bias    = (const float*)d_in[6];
    const float* A_log      = (const float*)d_in[7];
    const float* Dp         = (const float*)d_in[8];
    const float* norm_w     = (const float*)d_in[9];
    const float* out_proj_w = (const float*)d_in[10];
    const float* ln_w       = (const float*)d_in[11];
    const float* ln_b       = (const float*)d_in[12];
    const float* ffn_w1     = (const float*)d_in[13];
    const float* ffn_b1     = (const float*)d_in[14];
    const float* ffn_w2     = (const float*)d_in[15];
    const float* ffn_b2     = (const float*)d_in[16];
    const float* ffn_ln_w   = (const float*)d_in[17];
    const float* ffn_ln_b   = (const float*)d_in[18];
    float* out = (float*)d_out;

    float *p_zx, *p_O, *p_H2;
    __half *p_embh, *p_Gh, *p_Xh, *p_H1h, *p_winh, *p_wouth, *p_w1h, *p_w2h;
    cudaGetSymbolAddress((void**)&p_zx,   g_zxbcdt);
    cudaGetSymbolAddress((void**)&p_O,    g_O);
    cudaGetSymbolAddress((void**)&p_H2,   g_H2);
    cudaGetSymbolAddress((void**)&p_embh, g_emb_h);
    cudaGetSymbolAddress((void**)&p_Gh,   g_Gh);
    cudaGetSymbolAddress((void**)&p_Xh,   g_Xh);
    cudaGetSymbolAddress((void**)&p_H1h,  g_H1h);
    cudaGetSymbolAddress((void**)&p_winh, g_win_h);
    cudaGetSymbolAddress((void**)&p_wouth,g_wout_h);
    cudaGetSymbolAddress((void**)&p_w1h,  g_w1_h);
    cudaGetSymbolAddress((void**)&p_w2h,  g_w2_h);

    // opt-in to 60KB dynamic smem for the GEMM instantiations
    cudaFuncSetAttribute(h16gemm<0,0>, cudaFuncAttributeMaxDynamicSharedMemorySize, GEMM_SMEM);
    cudaFuncSetAttribute(h16gemm<2,1>, cudaFuncAttributeMaxDynamicSharedMemorySize, GEMM_SMEM);
    cudaFuncSetAttribute(h16gemm<1,0>, cudaFuncAttributeMaxDynamicSharedMemorySize, GEMM_SMEM);

    // 0) fp16 conversions
    cvt_kernel<<<(NTOK*DMODEL/4 + 255)/256, 256>>>(item_emb, p_embh, NTOK*DMODEL);
    cvt_inproj_kernel<<<(DINPROJ_PAD*DMODEL/4 + 255)/256, 256>>>(in_proj_w, p_winh);
    cvt_kernel<<<(DMODEL*DINNER/4 + 255)/256, 256>>>(out_proj_w, p_wouth, DMODEL*DINNER);
    cvt_kernel<<<(DFFN*DMODEL/4 + 255)/256, 256>>>(ffn_w1, p_w1h, DFFN*DMODEL);
    cvt_kernel<<<(DMODEL*DFFN/4 + 255)/256, 256>>>(ffn_w2, p_w2h, DMODEL*DFFN);

    // 1) in_proj (8192 x 2192 x 512)
    {
        dim3 grid(DINPROJ_PAD / 128, NTOK / 128);
        h16gemm<0,0><<<grid, 256, GEMM_SMEM>>>(p_embh, p_winh, nullptr, p_zx, NTOK, DINPROJ, DMODEL);
    }

    // 2) conv + silu
    {
        int total = 2 * NTOK * (CONVDIM / 4);
        conv_silu_kernel<<<(total + 255) / 256, 256>>>(conv_w, conv_b);
    }

    // 3) dt softplus
    {
        int total = NTOK * NHEADS;
        dt_kernel<<<(total + 255) / 256, 256>>>(dt_bias);
    }

    // 4) SSD
    ssd_local_kernel<<<4096, 32>>>(A_log, Dp);
    ssd_combine_kernel<<<256, 64>>>();
    ssd_fixup_mma_kernel<<<2*BATCH*NHEADS*(NCHUNK-1), 128>>>();

    // 5) gate + RMS + combine -> fp16 G
    gate_rms_combine_kernel<<<NTOK, 256>>>(norm_w);

    // 6) out_proj (8192 x 512 x 1024)
    {
        dim3 grid(DMODEL / 128, NTOK / 128);
        h16gemm<0,0><<<grid, 256, GEMM_SMEM>>>(p_Gh, p_wouth, nullptr, p_O, NTOK, DMODEL, DINNER);
    }

    // 7) LN1
    ln1_kernel<<<NTOK, 256>>>(item_emb, ln_w, ln_b);

    // 8) FFN1 (8192 x 2048 x 512)
    {
        dim3 grid(DFFN / 128, NTOK / 128);
        h16gemm<2,1><<<grid, 256, GEMM_SMEM>>>(p_Xh, p_w1h, ffn_b1, p_H1h, NTOK, DFFN, DMODEL);
    }

    // 9) FFN2 (8192 x 512 x 2048)
    {
        dim3 grid(DMODEL / 128, NTOK / 128);
        h16gemm<1,0><<<grid, 256, GEMM_SMEM>>>(p_H1h, p_w2h, ffn_b2, p_H2, NTOK, DMODEL, DFFN);
    }

    // 10) final LN
    ln2_kernel<<<NTOK, 256>>>(out, ffn_ln_w, ffn_ln_b);
}